// round 2
// baseline (speedup 1.0000x reference)
#include <cuda_runtime.h>
#include <math.h>

// Problem dims (fixed by the reference)
#define NB 8
#define NN 1024
#define ND 1024
#define NH 8
#define DH 128
#define SCALE_F 0.08838834764831845f  // 128^-0.5

// ---------------- scratch (device globals; no cudaMalloc allowed) ----------
__device__ float g_qkv[8ull * 1024 * 3072];   // 96 MB  [b*n][3072] = q_v|k_v|v
__device__ float g_qk [8ull * 1024 * 2048];   // 64 MB  [b*n][2048] = q_m|k_m
__device__ float g_sm [64ull * 1024 * 1024];  // 256 MB [b*h][i][j] raw m-scores
__device__ float g_mrow[64 * 1024];           // row max of S_m
__device__ float g_invl[64 * 1024];           // 1/rowsum(exp(S_m - max))
__device__ float g_ao  [8ull * 1024 * 1024];  // 32 MB  attention out [b*n][h*dh]

// ---------------- generic NN SGEMM: C[M,N] = A[M,K] @ B[K,N] (+bias) -------
// 128x128 tile, BK=8, 256 threads, 8x8 microtile
__global__ __launch_bounds__(256) void gemm_nn(
    const float* __restrict__ A, const float* __restrict__ Bm,
    float* __restrict__ C, int M, int N, int K, const float* __restrict__ bias)
{
    __shared__ float As[8][128];
    __shared__ float Bs[8][128];
    const int tid = threadIdx.x;
    const int tx = tid & 15, ty = tid >> 4;
    const int bm = blockIdx.y * 128, bn = blockIdx.x * 128;

    float acc[8][8];
#pragma unroll
    for (int i = 0; i < 8; i++)
#pragma unroll
        for (int j = 0; j < 8; j++) acc[i][j] = 0.f;

    const int arow = tid >> 1, ac4 = (tid & 1) * 4;   // A tile: 128 rows x 8 k
    const int brow = tid >> 5, bc4 = (tid & 31) * 4;  // B tile: 8 rows x 128 cols
    const float* Aptr = A + (size_t)(bm + arow) * K + ac4;
    const float* Bptr = Bm + (size_t)brow * N + bn + bc4;

    for (int k0 = 0; k0 < K; k0 += 8) {
        float4 av = *(const float4*)(Aptr + k0);
        float4 bv = *(const float4*)(Bptr + (size_t)k0 * N);
        __syncthreads();
        As[ac4 + 0][arow] = av.x; As[ac4 + 1][arow] = av.y;
        As[ac4 + 2][arow] = av.z; As[ac4 + 3][arow] = av.w;
        *(float4*)&Bs[brow][bc4] = bv;
        __syncthreads();
#pragma unroll
        for (int k = 0; k < 8; k++) {
            float a[8], b[8];
            *(float4*)(a)     = *(const float4*)&As[k][ty * 8];
            *(float4*)(a + 4) = *(const float4*)&As[k][ty * 8 + 4];
            *(float4*)(b)     = *(const float4*)&Bs[k][tx * 8];
            *(float4*)(b + 4) = *(const float4*)&Bs[k][tx * 8 + 4];
#pragma unroll
            for (int i = 0; i < 8; i++)
#pragma unroll
                for (int j = 0; j < 8; j++)
                    acc[i][j] = fmaf(a[i], b[j], acc[i][j]);
        }
    }
#pragma unroll
    for (int i = 0; i < 8; i++) {
        float* crow = C + (size_t)(bm + ty * 8 + i) * N + bn + tx * 8;
#pragma unroll
        for (int j = 0; j < 8; j += 4) {
            float4 v;
            v.x = acc[i][j]; v.y = acc[i][j + 1]; v.z = acc[i][j + 2]; v.w = acc[i][j + 3];
            if (bias) {
                int col = bn + tx * 8 + j;
                v.x += bias[col]; v.y += bias[col + 1];
                v.z += bias[col + 2]; v.w += bias[col + 3];
            }
            *(float4*)(crow + j) = v;
        }
    }
}

// ---------------- NT score GEMM: S[bh][i][j] = q_m[i]·k_m[j], K=128 -------
__global__ __launch_bounds__(256) void gemm_nt_scores()
{
    __shared__ float As[8][128];
    __shared__ float Bs[8][128];
    const int tid = threadIdx.x;
    const int tx = tid & 15, ty = tid >> 4;
    const int bm = blockIdx.y * 128, bn = blockIdx.x * 128;
    const int bh = blockIdx.z;
    const int b = bh >> 3, h = bh & 7;

    const float* Aq = g_qk + (size_t)b * NN * 2048 + h * 128;          // q_m rows, ld 2048
    const float* Bk = g_qk + (size_t)b * NN * 2048 + 1024 + h * 128;   // k_m rows, ld 2048
    float* C = g_sm + (size_t)bh * NN * NN;

    float acc[8][8];
#pragma unroll
    for (int i = 0; i < 8; i++)
#pragma unroll
        for (int j = 0; j < 8; j++) acc[i][j] = 0.f;

    const int arow = tid >> 1, ac4 = (tid & 1) * 4;

    for (int k0 = 0; k0 < 128; k0 += 8) {
        float4 av = *(const float4*)(Aq + (size_t)(bm + arow) * 2048 + k0 + ac4);
        float4 bv = *(const float4*)(Bk + (size_t)(bn + arow) * 2048 + k0 + ac4);
        __syncthreads();
        As[ac4 + 0][arow] = av.x; As[ac4 + 1][arow] = av.y;
        As[ac4 + 2][arow] = av.z; As[ac4 + 3][arow] = av.w;
        Bs[ac4 + 0][arow] = bv.x; Bs[ac4 + 1][arow] = bv.y;
        Bs[ac4 + 2][arow] = bv.z; Bs[ac4 + 3][arow] = bv.w;
        __syncthreads();
#pragma unroll
        for (int k = 0; k < 8; k++) {
            float a[8], bb[8];
            *(float4*)(a)      = *(const float4*)&As[k][ty * 8];
            *(float4*)(a + 4)  = *(const float4*)&As[k][ty * 8 + 4];
            *(float4*)(bb)     = *(const float4*)&Bs[k][tx * 8];
            *(float4*)(bb + 4) = *(const float4*)&Bs[k][tx * 8 + 4];
#pragma unroll
            for (int i = 0; i < 8; i++)
#pragma unroll
                for (int j = 0; j < 8; j++)
                    acc[i][j] = fmaf(a[i], bb[j], acc[i][j]);
        }
    }
#pragma unroll
    for (int i = 0; i < 8; i++) {
        float* crow = C + (size_t)(bm + ty * 8 + i) * NN + bn + tx * 8;
#pragma unroll
        for (int j = 0; j < 8; j += 4) {
            float4 v;
            v.x = acc[i][j]; v.y = acc[i][j + 1]; v.z = acc[i][j + 2]; v.w = acc[i][j + 3];
            *(float4*)(crow + j) = v;
        }
    }
}

// ---------------- row stats for inner softmax: max and 1/sumexp ------------
__global__ __launch_bounds__(256) void row_stats()
{
    const int row = blockIdx.x;          // 0 .. 65535
    const float* p = g_sm + (size_t)row * NN;
    const int tid = threadIdx.x;
    __shared__ float red[256];

    float m = -1e30f;
    for (int j = tid; j < NN; j += 256) m = fmaxf(m, p[j]);
    red[tid] = m; __syncthreads();
    for (int s = 128; s > 0; s >>= 1) {
        if (tid < s) red[tid] = fmaxf(red[tid], red[tid + s]);
        __syncthreads();
    }
    const float mv = red[0];
    __syncthreads();

    float sum = 0.f;
    for (int j = tid; j < NN; j += 256) sum += __expf(p[j] - mv);
    red[tid] = sum; __syncthreads();
    for (int s = 128; s > 0; s >>= 1) {
        if (tid < s) red[tid] += red[tid + s];
        __syncthreads();
    }
    if (tid == 0) { g_mrow[row] = mv; g_invl[row] = 1.f / red[0]; }
}

// ---------------- fused flash attention ------------------------------------
// block = (64-query tile, head, batch); 256 threads
// score threads: (ty,tx) -> 4x4 of 64x64; O threads: rows ty*4+[0,4), cols tx*8+[0,8)
struct AttnSmem {
    float QvT[128][68];
    float KvT[128][68];
    float V[64][132];
    float P[64][68];
    float red[64][16];
    float mi[64], invli[64], mrun[64], lrun[64], alpha[64], mnew[64];
};

__global__ __launch_bounds__(256) void attn_kernel(const float* __restrict__ gl)
{
    extern __shared__ __align__(16) char smraw[];
    AttnSmem& s = *reinterpret_cast<AttnSmem*>(smraw);
    const int tid = threadIdx.x;
    const int tx = tid & 15, ty = tid >> 4;
    const int i0 = blockIdx.x * 64;
    const int h = blockIdx.y, b = blockIdx.z;
    const size_t bh = (size_t)(b * NH + h);

    const float* qv = g_qkv + (size_t)b * NN * 3072 + h * 128;
    const float* kv = g_qkv + (size_t)b * NN * 3072 + 1024 + h * 128;
    const float* vv = g_qkv + (size_t)b * NN * 3072 + 2048 + h * 128;
    const float* Sm = g_sm + bh * NN * NN;
    const float* GL = gl + bh * NN * NN;

    // load Q_v tile transposed (64 rows x 128 d)
#pragma unroll
    for (int it = 0; it < 8; it++) {
        int idx = tid + it * 256;          // 2048 float4 slots
        int row = idx >> 5;
        int d4 = (idx & 31) << 2;
        float4 a = *(const float4*)(qv + (size_t)(i0 + row) * 3072 + d4);
        s.QvT[d4 + 0][row] = a.x; s.QvT[d4 + 1][row] = a.y;
        s.QvT[d4 + 2][row] = a.z; s.QvT[d4 + 3][row] = a.w;
    }
    if (tid < 64) {
        s.mi[tid]    = g_mrow[bh * NN + i0 + tid];
        s.invli[tid] = g_invl[bh * NN + i0 + tid];
        s.mrun[tid] = -1e30f;
        s.lrun[tid] = 0.f;
    }

    float O[4][8];
#pragma unroll
    for (int r = 0; r < 4; r++)
#pragma unroll
        for (int c = 0; c < 8; c++) O[r][c] = 0.f;

    const int srow = ty * 4, scol = tx * 4, ocol = tx * 8;

    for (int j0 = 0; j0 < NN; j0 += 64) {
        __syncthreads();   // prior iter done with K/V/P; Q/stat loads visible
        // load K_v (transposed) and V for this j tile
#pragma unroll
        for (int it = 0; it < 8; it++) {
            int idx = tid + it * 256;
            int row = idx >> 5;
            int d4 = (idx & 31) << 2;
            float4 a = *(const float4*)(kv + (size_t)(j0 + row) * 3072 + d4);
            s.KvT[d4 + 0][row] = a.x; s.KvT[d4 + 1][row] = a.y;
            s.KvT[d4 + 2][row] = a.z; s.KvT[d4 + 3][row] = a.w;
            float4 c = *(const float4*)(vv + (size_t)(j0 + row) * 3072 + d4);
            *(float4*)&s.V[row][d4] = c;
        }
        // prefetch S_m and g_l tiles for this thread (latency hidden by score GEMM)
        float smv[4][4], glv[4][4];
#pragma unroll
        for (int r = 0; r < 4; r++) {
            float4 t0 = *(const float4*)(Sm + (size_t)(i0 + srow + r) * NN + j0 + scol);
            smv[r][0] = t0.x; smv[r][1] = t0.y; smv[r][2] = t0.z; smv[r][3] = t0.w;
            float4 t1 = *(const float4*)(GL + (size_t)(i0 + srow + r) * NN + j0 + scol);
            glv[r][0] = t1.x; glv[r][1] = t1.y; glv[r][2] = t1.z; glv[r][3] = t1.w;
        }
        __syncthreads();

        // p_v score tile: 64x64x128
        float sv[4][4];
#pragma unroll
        for (int r = 0; r < 4; r++)
#pragma unroll
            for (int c = 0; c < 4; c++) sv[r][c] = 0.f;
#pragma unroll 4
        for (int d = 0; d < 128; d++) {
            float4 q4 = *(const float4*)&s.QvT[d][srow];
            float4 k4 = *(const float4*)&s.KvT[d][scol];
            float qa[4] = {q4.x, q4.y, q4.z, q4.w};
            float ka[4] = {k4.x, k4.y, k4.z, k4.w};
#pragma unroll
            for (int r = 0; r < 4; r++)
#pragma unroll
                for (int c = 0; c < 4; c++)
                    sv[r][c] = fmaf(qa[r], ka[c], sv[r][c]);
        }

        // dots = p_m * p_v * scale + g_l ; partial row max
        float dv[4][4];
#pragma unroll
        for (int r = 0; r < 4; r++) {
            float mi_r = s.mi[srow + r], il_r = s.invli[srow + r];
            float rmax = -1e30f;
#pragma unroll
            for (int c = 0; c < 4; c++) {
                float pm = __expf(smv[r][c] - mi_r) * il_r;
                float d = fmaf(pm * sv[r][c], SCALE_F, glv[r][c]);
                dv[r][c] = d;
                rmax = fmaxf(rmax, d);
            }
            s.red[srow + r][tx] = rmax;
        }
        __syncthreads();
        if (tid < 64) {
            float tm = -1e30f;
#pragma unroll
            for (int t = 0; t < 16; t++) tm = fmaxf(tm, s.red[tid][t]);
            float mo = s.mrun[tid];
            float mn = fmaxf(mo, tm);
            s.mnew[tid] = mn;
            s.alpha[tid] = __expf(mo - mn);
            s.mrun[tid] = mn;
        }
        __syncthreads();
        // P = exp(dots - mnew), partial row sums; rescale O
#pragma unroll
        for (int r = 0; r < 4; r++) {
            float mn = s.mnew[srow + r];
            float ps = 0.f;
            float4 pw;
            float p0 = __expf(dv[r][0] - mn);
            float p1 = __expf(dv[r][1] - mn);
            float p2 = __expf(dv[r][2] - mn);
            float p3 = __expf(dv[r][3] - mn);
            pw.x = p0; pw.y = p1; pw.z = p2; pw.w = p3;
            ps = p0 + p1 + p2 + p3;
            *(float4*)&s.P[srow + r][scol] = pw;
            s.red[srow + r][tx] = ps;
            float al = s.alpha[srow + r];
#pragma unroll
            for (int c = 0; c < 8; c++) O[r][c] *= al;
        }
        __syncthreads();
        if (tid < 64) {
            float ssum = 0.f;
#pragma unroll
            for (int t = 0; t < 16; t++) ssum += s.red[tid][t];
            s.lrun[tid] = s.lrun[tid] * s.alpha[tid] + ssum;
        }
        // O += P @ V  (P rows match this thread's O rows)
        for (int k4 = 0; k4 < 64; k4 += 4) {
            float pr[4][4];
#pragma unroll
            for (int r = 0; r < 4; r++) {
                float4 t = *(const float4*)&s.P[srow + r][k4];
                pr[r][0] = t.x; pr[r][1] = t.y; pr[r][2] = t.z; pr[r][3] = t.w;
            }
#pragma unroll
            for (int kk = 0; kk < 4; kk++) {
                float4 v0 = *(const float4*)&s.V[k4 + kk][ocol];
                float4 v1 = *(const float4*)&s.V[k4 + kk][ocol + 4];
                float vb[8] = {v0.x, v0.y, v0.z, v0.w, v1.x, v1.y, v1.z, v1.w};
#pragma unroll
                for (int r = 0; r < 4; r++)
#pragma unroll
                    for (int c = 0; c < 8; c++)
                        O[r][c] = fmaf(pr[r][kk], vb[c], O[r][c]);
            }
        }
    }
    __syncthreads();   // lrun final
#pragma unroll
    for (int r = 0; r < 4; r++) {
        float inv = 1.f / s.lrun[srow + r];
        float* orow = g_ao + (size_t)(b * NN + i0 + srow + r) * (NH * DH) + h * 128 + ocol;
        float4 w0, w1;
        w0.x = O[r][0] * inv; w0.y = O[r][1] * inv; w0.z = O[r][2] * inv; w0.w = O[r][3] * inv;
        w1.x = O[r][4] * inv; w1.y = O[r][5] * inv; w1.z = O[r][6] * inv; w1.w = O[r][7] * inv;
        *(float4*)(orow) = w0;
        *(float4*)(orow + 4) = w1;
    }
}

// ---------------- launch ----------------------------------------------------
extern "C" void kernel_launch(void* const* d_in, const int* in_sizes, int n_in,
                              void* d_out, int out_size)
{
    const float* s_v   = (const float*)d_in[0];
    const float* s_m   = (const float*)d_in[1];
    const float* g_l   = (const float*)d_in[2];
    const float* W_qkv = (const float*)d_in[3];
    const float* W_qk  = (const float*)d_in[4];
    const float* W_out = (const float*)d_in[5];
    const float* b_out = (const float*)d_in[6];
    float* out = (float*)d_out;

    float *p_qkv, *p_qk, *p_ao;
    cudaGetSymbolAddress((void**)&p_qkv, g_qkv);
    cudaGetSymbolAddress((void**)&p_qk,  g_qk);
    cudaGetSymbolAddress((void**)&p_ao,  g_ao);

    // 1. QKV projection: [8192,1024] @ [1024,3072]
    gemm_nn<<<dim3(3072 / 128, 8192 / 128), 256>>>(s_v, W_qkv, p_qkv, 8192, 3072, 1024, nullptr);
    // 2. QK projection: [8192,1024] @ [1024,2048]
    gemm_nn<<<dim3(2048 / 128, 8192 / 128), 256>>>(s_m, W_qk, p_qk, 8192, 2048, 1024, nullptr);
    // 3. m-stream scores S_m = q_m k_m^T per (b,h)
    gemm_nt_scores<<<dim3(8, 8, 64), 256>>>();
    // 4. inner-softmax row stats
    row_stats<<<64 * 1024, 256>>>();
    // 5. fused attention
    cudaFuncSetAttribute(attn_kernel, cudaFuncAttributeMaxDynamicSharedMemorySize,
                         (int)sizeof(AttnSmem));
    attn_kernel<<<dim3(16, NH, NB), 256, sizeof(AttnSmem)>>>(g_l);
    // 6. output projection + bias
    gemm_nn<<<dim3(1024 / 128, 8192 / 128), 256>>>(p_ao, W_out, out, 8192, 1024, 1024, b_out);
}

// round 4
// speedup vs baseline: 1.4956x; 1.4956x over previous
#include <cuda_runtime.h>
#include <cuda_bf16.h>
#include <cstdint>
#include <math.h>

#define NB 8
#define NN 1024
#define NH 8
#define SCALE_F 0.08838834764831845f  // 128^-0.5

// ---------------- scratch (device globals; no cudaMalloc allowed) ----------
__device__ float g_qkv[8ull * 1024 * 3072];   // [b*n][3072] = q_v|k_v|v
__device__ float g_qk [8ull * 1024 * 2048];   // [b*n][2048] = q_m|k_m
__device__ float g_sm [64ull * 1024 * 1024];  // [b*h][i][j] raw m-scores
__device__ float g_mrow[64 * 1024];
__device__ float g_invl[64 * 1024];
__device__ float g_ao  [8ull * 1024 * 1024];  // [b*n][h*dh]

// ======================= helpers ===========================================
__device__ __forceinline__ uint32_t smem_u32(const void* p) {
    uint32_t a;
    asm("{ .reg .u64 t; cvta.to.shared.u64 t, %1; cvt.u32.u64 %0, t; }"
        : "=r"(a) : "l"(p));
    return a;
}

__device__ __forceinline__ void ldsm4(uint32_t* r, uint32_t addr) {
    asm volatile("ldmatrix.sync.aligned.m8n8.x4.shared.b16 {%0,%1,%2,%3}, [%4];"
                 : "=r"(r[0]), "=r"(r[1]), "=r"(r[2]), "=r"(r[3]) : "r"(addr));
}

__device__ __forceinline__ void mma16816(float* d, const uint32_t* a, const uint32_t* b) {
    asm volatile(
        "mma.sync.aligned.m16n8k16.row.col.f32.bf16.bf16.f32 "
        "{%0,%1,%2,%3}, {%4,%5,%6,%7}, {%8,%9}, {%0,%1,%2,%3};"
        : "+f"(d[0]), "+f"(d[1]), "+f"(d[2]), "+f"(d[3])
        : "r"(a[0]), "r"(a[1]), "r"(a[2]), "r"(a[3]), "r"(b[0]), "r"(b[1]));
}

__device__ __forceinline__ uint32_t sw_off(uint32_t off) {
    return off ^ ((off >> 3) & 0x70);
}
__device__ __forceinline__ void st8_sw(char* base, uint32_t off, uint32_t a, uint32_t b) {
    *(uint2*)(base + sw_off(off)) = make_uint2(a, b);
}
__device__ __forceinline__ uint32_t pack2(float a, float b) {
    __nv_bfloat162 t;
    t.x = __float2bfloat16(a);
    t.y = __float2bfloat16(b);
    return *(uint32_t*)&t;
}
__device__ __forceinline__ void split4(const float4& v, uint32_t& h01, uint32_t& h23,
                                       uint32_t& l01, uint32_t& l23) {
    __nv_bfloat16 b0 = __float2bfloat16(v.x);
    __nv_bfloat16 b1 = __float2bfloat16(v.y);
    __nv_bfloat16 b2 = __float2bfloat16(v.z);
    __nv_bfloat16 b3 = __float2bfloat16(v.w);
    __nv_bfloat162 h; h.x = b0; h.y = b1; h01 = *(uint32_t*)&h;
    h.x = b2; h.y = b3; h23 = *(uint32_t*)&h;
    l01 = pack2(v.x - __bfloat162float(b0), v.y - __bfloat162float(b1));
    l23 = pack2(v.z - __bfloat162float(b2), v.w - __bfloat162float(b3));
}

// ======================= mma.sync GEMM =====================================
// C[M,N] = A[M,K] * B  (BT=true: B is [K,N] row-major; BT=false: B is [N,K])
// CTA tile 128x128, K chunk 64, 512 threads (16 warps, 4x4 warp grid, 32x32/warp)
// bf16x3 split: AH*BH + AH*BL + AL*BH, fp32 accumulators.
#define ST_BYTES  65536          // one stage: AH|AL|BH|BL, 16KB each (SW128 rows)
#define OFF_AH    0
#define OFF_AL    16384
#define OFF_BH    32768
#define OFF_BL    49152
#define GEMM_SMEM (1024 + 2 * ST_BYTES)

template<bool BT, bool BIAS>
__global__ __launch_bounds__(512, 1) void gemm_mma(
    const float* __restrict__ A, int lda, size_t Azb, size_t Azh,
    const float* __restrict__ B, int ldb, size_t Bzb, size_t Bzh,
    float* __restrict__ C, int ldc, size_t Cz,
    int K, const float* __restrict__ bias)
{
    extern __shared__ char smraw[];
    uint32_t raw = smem_u32(smraw);
    char* sm = smraw + ((1024u - (raw & 1023u)) & 1023u);
    const uint32_t smb = smem_u32(sm);

    const int tid = threadIdx.x;
    const int wid = tid >> 5, lane = tid & 31;
    const int wm = wid & 3, wn = wid >> 2;      // 4x4 warp grid
    const int bn = blockIdx.x * 128, bm = blockIdx.y * 128;
    const int z = blockIdx.z;

    A += (size_t)(z >> 3) * Azb + (size_t)(z & 7) * Azh;
    B += (size_t)(z >> 3) * Bzb + (size_t)(z & 7) * Bzh;
    C += (size_t)z * Cz;

    const float* At = A + (size_t)bm * lda;
    const float* Bt = BT ? (B + bn) : (B + (size_t)bn * ldb);

    float acc[2][4][4];
#pragma unroll
    for (int mt = 0; mt < 2; mt++)
#pragma unroll
        for (int nt = 0; nt < 4; nt++)
#pragma unroll
            for (int i = 0; i < 4; i++) acc[mt][nt][i] = 0.f;

    const int nchunks = K >> 6;
    float4 pa[4], pb[4];

    // ---- prefetch-chunk global loads (A: 4 fl4/thread; B: 4 fl4/thread) ---
    // A and non-BT B: idx = tid + it*512 -> row = idx>>4, k4 = (idx&15)<<2
    // BT B: idx = tid -> k4 = (idx&15)<<2, n4 = (idx>>4)<<2 (4 k-rows loaded)
#define LOAD_A(c) {                                                            \
        int _k0 = (c) << 6;                                                    \
        _Pragma("unroll")                                                      \
        for (int it = 0; it < 4; it++) {                                       \
            int idx = tid + it * 512;                                          \
            int row = idx >> 4, k4 = (idx & 15) << 2;                          \
            pa[it] = *(const float4*)(At + (size_t)row * lda + _k0 + k4);      \
        }                                                                      \
    }
#define LOAD_B(c) {                                                            \
        int _k0 = (c) << 6;                                                    \
        if (BT) {                                                              \
            int k4 = (tid & 15) << 2, n4 = (tid >> 4) << 2;                    \
            _Pragma("unroll")                                                  \
            for (int i = 0; i < 4; i++)                                        \
                pb[i] = *(const float4*)(Bt + (size_t)(_k0 + k4 + i) * ldb + n4); \
        } else {                                                               \
            _Pragma("unroll")                                                  \
            for (int it = 0; it < 4; it++) {                                   \
                int idx = tid + it * 512;                                      \
                int row = idx >> 4, k4 = (idx & 15) << 2;                      \
                pb[it] = *(const float4*)(Bt + (size_t)row * ldb + _k0 + k4);  \
            }                                                                  \
        }                                                                      \
    }
#define STORE_STAGE(buf) {                                                     \
        char* st = sm + (buf) * ST_BYTES;                                      \
        _Pragma("unroll")                                                      \
        for (int it = 0; it < 4; it++) {                                       \
            int idx = tid + it * 512;                                          \
            int row = idx >> 4, k4 = (idx & 15) << 2;                          \
            uint32_t h01, h23, l01, l23;                                       \
            split4(pa[it], h01, h23, l01, l23);                                \
            uint32_t off = row * 128 + k4 * 2;                                 \
            st8_sw(st + OFF_AH, off, h01, h23);                                \
            st8_sw(st + OFF_AL, off, l01, l23);                                \
        }                                                                      \
        if (BT) {                                                              \
            int k4 = (tid & 15) << 2, n4 = (tid >> 4) << 2;                    \
            const float* rr[4] = {&pb[0].x, &pb[1].x, &pb[2].x, &pb[3].x};     \
            _Pragma("unroll")                                                  \
            for (int i = 0; i < 4; i++) {                                      \
                float4 col;                                                    \
                col.x = rr[0][i]; col.y = rr[1][i];                            \
                col.z = rr[2][i]; col.w = rr[3][i];                            \
                uint32_t h01, h23, l01, l23;                                   \
                split4(col, h01, h23, l01, l23);                               \
                uint32_t off = (n4 + i) * 128 + k4 * 2;                        \
                st8_sw(st + OFF_BH, off, h01, h23);                            \
                st8_sw(st + OFF_BL, off, l01, l23);                            \
            }                                                                  \
        } else {                                                               \
            _Pragma("unroll")                                                  \
            for (int it = 0; it < 4; it++) {                                   \
                int idx = tid + it * 512;                                      \
                int row = idx >> 4, k4 = (idx & 15) << 2;                      \
                uint32_t h01, h23, l01, l23;                                   \
                split4(pb[it], h01, h23, l01, l23);                            \
                uint32_t off = row * 128 + k4 * 2;                             \
                st8_sw(st + OFF_BH, off, h01, h23);                            \
                st8_sw(st + OFF_BL, off, l01, l23);                            \
            }                                                                  \
        }                                                                      \
    }

    LOAD_A(0); LOAD_B(0);
    STORE_STAGE(0);
    __syncthreads();

    // fragment address components (constant across chunks)
    const uint32_t arow0 = wm * 32 + (lane & 15);
    const uint32_t akhalf = (lane >> 4) * 16;          // bytes
    const uint32_t bg = lane >> 3, br = lane & 7;
    const uint32_t brow0 = wn * 32 + (bg >> 1) * 8 + br;
    const uint32_t bkhalf = (bg & 1) * 16;             // bytes

    for (int c = 0; c < nchunks; ++c) {
        const uint32_t so = smb + (c & 1) * ST_BYTES;
        if (c + 1 < nchunks) { LOAD_A(c + 1); LOAD_B(c + 1); }

        const uint32_t aHb = so + OFF_AH, aLb = so + OFF_AL;
        const uint32_t bHb = so + OFF_BH, bLb = so + OFF_BL;

#pragma unroll
        for (int k16 = 0; k16 < 4; ++k16) {
            const uint32_t kb = k16 * 32;
            uint32_t offA0 = sw_off(arow0 * 128 + kb + akhalf);
            uint32_t offA1 = sw_off((arow0 + 16) * 128 + kb + akhalf);
            uint32_t offB0 = sw_off(brow0 * 128 + kb + bkhalf);
            uint32_t offB1 = sw_off((brow0 + 16) * 128 + kb + bkhalf);

            uint32_t aH[2][4], aL[2][4];
            ldsm4(aH[0], aHb + offA0); ldsm4(aH[1], aHb + offA1);
            ldsm4(aL[0], aLb + offA0); ldsm4(aL[1], aLb + offA1);

            uint32_t bH01[4], bH23[4], bL01[4], bL23[4];
            ldsm4(bH01, bHb + offB0); ldsm4(bH23, bHb + offB1);
            ldsm4(bL01, bLb + offB0); ldsm4(bL23, bLb + offB1);

#pragma unroll
            for (int mt = 0; mt < 2; mt++) {
#pragma unroll
                for (int nt = 0; nt < 4; nt++) {
                    const uint32_t* bh = (nt < 2) ? &bH01[(nt & 1) * 2] : &bH23[(nt & 1) * 2];
                    const uint32_t* bl = (nt < 2) ? &bL01[(nt & 1) * 2] : &bL23[(nt & 1) * 2];
                    mma16816(acc[mt][nt], aH[mt], bh);
                    mma16816(acc[mt][nt], aH[mt], bl);
                    mma16816(acc[mt][nt], aL[mt], bh);
                }
            }
        }
        __syncthreads();
        if (c + 1 < nchunks) STORE_STAGE((c + 1) & 1);
        __syncthreads();
    }

    // ---- epilogue: registers -> gmem (each quad covers a 32B sector) ------
    const int rgrp = lane >> 2, cpair = (lane & 3) * 2;
#pragma unroll
    for (int mt = 0; mt < 2; mt++) {
#pragma unroll
        for (int nt = 0; nt < 4; nt++) {
            int row0 = bm + wm * 32 + mt * 16 + rgrp;
            int col = bn + wn * 32 + nt * 8 + cpair;
            float b0 = 0.f, b1 = 0.f;
            if (BIAS) { b0 = bias[col]; b1 = bias[col + 1]; }
            float2 v0, v1;
            v0.x = acc[mt][nt][0] + b0; v0.y = acc[mt][nt][1] + b1;
            v1.x = acc[mt][nt][2] + b0; v1.y = acc[mt][nt][3] + b1;
            *(float2*)(C + (size_t)row0 * ldc + col) = v0;
            *(float2*)(C + (size_t)(row0 + 8) * ldc + col) = v1;
        }
    }
#undef LOAD_A
#undef LOAD_B
#undef STORE_STAGE
}

// ---------------- row stats: max and 1/sumexp, float4 + shuffles -----------
__global__ __launch_bounds__(256) void row_stats()
{
    const int row = blockIdx.x;
    const float4* p = (const float4*)(g_sm + (size_t)row * NN);
    const int tid = threadIdx.x;
    __shared__ float red8[8];
    __shared__ float bval;

    float4 v = p[tid];
    float m = fmaxf(fmaxf(v.x, v.y), fmaxf(v.z, v.w));
#pragma unroll
    for (int o = 16; o > 0; o >>= 1) m = fmaxf(m, __shfl_xor_sync(~0u, m, o));
    if ((tid & 31) == 0) red8[tid >> 5] = m;
    __syncthreads();
    if (tid == 0) {
        float t = red8[0];
#pragma unroll
        for (int i = 1; i < 8; ++i) t = fmaxf(t, red8[i]);
        bval = t;
    }
    __syncthreads();
    const float mv = bval;

    float s = __expf(v.x - mv) + __expf(v.y - mv) + __expf(v.z - mv) + __expf(v.w - mv);
#pragma unroll
    for (int o = 16; o > 0; o >>= 1) s += __shfl_xor_sync(~0u, s, o);
    if ((tid & 31) == 0) red8[tid >> 5] = s;
    __syncthreads();
    if (tid == 0) {
        float t = 0.f;
#pragma unroll
        for (int i = 0; i < 8; ++i) t += red8[i];
        g_mrow[row] = mv;
        g_invl[row] = 1.f / t;
    }
}

// ---------------- fused flash attention (unchanged, passing) ---------------
struct AttnSmem {
    float QvT[128][68];
    float KvT[128][68];
    float V[64][132];
    float P[64][68];
    float red[64][16];
    float mi[64], invli[64], mrun[64], lrun[64], alpha[64], mnew[64];
};

__global__ __launch_bounds__(256) void attn_kernel(const float* __restrict__ gl)
{
    extern __shared__ __align__(16) char smraw[];
    AttnSmem& s = *reinterpret_cast<AttnSmem*>(smraw);
    const int tid = threadIdx.x;
    const int tx = tid & 15, ty = tid >> 4;
    const int i0 = blockIdx.x * 64;
    const int h = blockIdx.y, b = blockIdx.z;
    const size_t bh = (size_t)(b * NH + h);

    const float* qv = g_qkv + (size_t)b * NN * 3072 + h * 128;
    const float* kv = g_qkv + (size_t)b * NN * 3072 + 1024 + h * 128;
    const float* vv = g_qkv + (size_t)b * NN * 3072 + 2048 + h * 128;
    const float* Sm = g_sm + bh * NN * NN;
    const float* GL = gl + bh * NN * NN;

#pragma unroll
    for (int it = 0; it < 8; it++) {
        int idx = tid + it * 256;
        int row = idx >> 5;
        int d4 = (idx & 31) << 2;
        float4 a = *(const float4*)(qv + (size_t)(i0 + row) * 3072 + d4);
        s.QvT[d4 + 0][row] = a.x; s.QvT[d4 + 1][row] = a.y;
        s.QvT[d4 + 2][row] = a.z; s.QvT[d4 + 3][row] = a.w;
    }
    if (tid < 64) {
        s.mi[tid]    = g_mrow[bh * NN + i0 + tid];
        s.invli[tid] = g_invl[bh * NN + i0 + tid];
        s.mrun[tid] = -1e30f;
        s.lrun[tid] = 0.f;
    }

    float O[4][8];
#pragma unroll
    for (int r = 0; r < 4; r++)
#pragma unroll
        for (int c = 0; c < 8; c++) O[r][c] = 0.f;

    const int srow = ty * 4, scol = tx * 4, ocol = tx * 8;

    for (int j0 = 0; j0 < NN; j0 += 64) {
        __syncthreads();
#pragma unroll
        for (int it = 0; it < 8; it++) {
            int idx = tid + it * 256;
            int row = idx >> 5;
            int d4 = (idx & 31) << 2;
            float4 a = *(const float4*)(kv + (size_t)(j0 + row) * 3072 + d4);
            s.KvT[d4 + 0][row] = a.x; s.KvT[d4 + 1][row] = a.y;
            s.KvT[d4 + 2][row] = a.z; s.KvT[d4 + 3][row] = a.w;
            float4 c = *(const float4*)(vv + (size_t)(j0 + row) * 3072 + d4);
            *(float4*)&s.V[row][d4] = c;
        }
        float smv[4][4], glv[4][4];
#pragma unroll
        for (int r = 0; r < 4; r++) {
            float4 t0 = *(const float4*)(Sm + (size_t)(i0 + srow + r) * NN + j0 + scol);
            smv[r][0] = t0.x; smv[r][1] = t0.y; smv[r][2] = t0.z; smv[r][3] = t0.w;
            float4 t1 = *(const float4*)(GL + (size_t)(i0 + srow + r) * NN + j0 + scol);
            glv[r][0] = t1.x; glv[r][1] = t1.y; glv[r][2] = t1.z; glv[r][3] = t1.w;
        }
        __syncthreads();

        float sv[4][4];
#pragma unroll
        for (int r = 0; r < 4; r++)
#pragma unroll
            for (int c = 0; c < 4; c++) sv[r][c] = 0.f;
#pragma unroll 4
        for (int d = 0; d < 128; d++) {
            float4 q4 = *(const float4*)&s.QvT[d][srow];
            float4 k4 = *(const float4*)&s.KvT[d][scol];
            float qa[4] = {q4.x, q4.y, q4.z, q4.w};
            float ka[4] = {k4.x, k4.y, k4.z, k4.w};
#pragma unroll
            for (int r = 0; r < 4; r++)
#pragma unroll
                for (int c = 0; c < 4; c++)
                    sv[r][c] = fmaf(qa[r], ka[c], sv[r][c]);
        }

        float dv[4][4];
#pragma unroll
        for (int r = 0; r < 4; r++) {
            float mi_r = s.mi[srow + r], il_r = s.invli[srow + r];
            float rmax = -1e30f;
#pragma unroll
            for (int c = 0; c < 4; c++) {
                float pm = __expf(smv[r][c] - mi_r) * il_r;
                float d = fmaf(pm * sv[r][c], SCALE_F, glv[r][c]);
                dv[r][c] = d;
                rmax = fmaxf(rmax, d);
            }
            s.red[srow + r][tx] = rmax;
        }
        __syncthreads();
        if (tid < 64) {
            float tm = -1e30f;
#pragma unroll
            for (int t = 0; t < 16; t++) tm = fmaxf(tm, s.red[tid][t]);
            float mo = s.mrun[tid];
            float mn = fmaxf(mo, tm);
            s.mnew[tid] = mn;
            s.alpha[tid] = __expf(mo - mn);
            s.mrun[tid] = mn;
        }
        __syncthreads();
#pragma unroll
        for (int r = 0; r < 4; r++) {
            float mn = s.mnew[srow + r];
            float4 pw;
            float p0 = __expf(dv[r][0] - mn);
            float p1 = __expf(dv[r][1] - mn);
            float p2 = __expf(dv[r][2] - mn);
            float p3 = __expf(dv[r][3] - mn);
            pw.x = p0; pw.y = p1; pw.z = p2; pw.w = p3;
            *(float4*)&s.P[srow + r][scol] = pw;
            s.red[srow + r][tx] = p0 + p1 + p2 + p3;
            float al = s.alpha[srow + r];
#pragma unroll
            for (int c = 0; c < 8; c++) O[r][c] *= al;
        }
        __syncthreads();
        if (tid < 64) {
            float ssum = 0.f;
#pragma unroll
            for (int t = 0; t < 16; t++) ssum += s.red[tid][t];
            s.lrun[tid] = s.lrun[tid] * s.alpha[tid] + ssum;
        }
        for (int k4 = 0; k4 < 64; k4 += 4) {
            float pr[4][4];
#pragma unroll
            for (int r = 0; r < 4; r++) {
                float4 t = *(const float4*)&s.P[srow + r][k4];
                pr[r][0] = t.x; pr[r][1] = t.y; pr[r][2] = t.z; pr[r][3] = t.w;
            }
#pragma unroll
            for (int kk = 0; kk < 4; kk++) {
                float4 v0 = *(const float4*)&s.V[k4 + kk][ocol];
                float4 v1 = *(const float4*)&s.V[k4 + kk][ocol + 4];
                float vb[8] = {v0.x, v0.y, v0.z, v0.w, v1.x, v1.y, v1.z, v1.w};
#pragma unroll
                for (int r = 0; r < 4; r++)
#pragma unroll
                    for (int c = 0; c < 8; c++)
                        O[r][c] = fmaf(pr[r][kk], vb[c], O[r][c]);
            }
        }
    }
    __syncthreads();
#pragma unroll
    for (int r = 0; r < 4; r++) {
        float inv = 1.f / s.lrun[srow + r];
        float* orow = g_ao + (size_t)(b * NN + i0 + srow + r) * 1024 + h * 128 + ocol;
        float4 w0, w1;
        w0.x = O[r][0] * inv; w0.y = O[r][1] * inv; w0.z = O[r][2] * inv; w0.w = O[r][3] * inv;
        w1.x = O[r][4] * inv; w1.y = O[r][5] * inv; w1.z = O[r][6] * inv; w1.w = O[r][7] * inv;
        *(float4*)(orow) = w0;
        *(float4*)(orow + 4) = w1;
    }
}

// ---------------- launch ----------------------------------------------------
extern "C" void kernel_launch(void* const* d_in, const int* in_sizes, int n_in,
                              void* d_out, int out_size)
{
    const float* s_v   = (const float*)d_in[0];
    const float* s_m   = (const float*)d_in[1];
    const float* g_l   = (const float*)d_in[2];
    const float* W_qkv = (const float*)d_in[3];
    const float* W_qk  = (const float*)d_in[4];
    const float* W_out = (const float*)d_in[5];
    const float* b_out = (const float*)d_in[6];
    float* out = (float*)d_out;

    float *p_qkv, *p_qk, *p_sm, *p_ao;
    cudaGetSymbolAddress((void**)&p_qkv, g_qkv);
    cudaGetSymbolAddress((void**)&p_qk,  g_qk);
    cudaGetSymbolAddress((void**)&p_sm,  g_sm);
    cudaGetSymbolAddress((void**)&p_ao,  g_ao);

    cudaFuncSetAttribute(gemm_mma<true, false>,
                         cudaFuncAttributeMaxDynamicSharedMemorySize, GEMM_SMEM);
    cudaFuncSetAttribute(gemm_mma<true, true>,
                         cudaFuncAttributeMaxDynamicSharedMemorySize, GEMM_SMEM);
    cudaFuncSetAttribute(gemm_mma<false, false>,
                         cudaFuncAttributeMaxDynamicSharedMemorySize, GEMM_SMEM);
    cudaFuncSetAttribute(attn_kernel,
                         cudaFuncAttributeMaxDynamicSharedMemorySize, (int)sizeof(AttnSmem));

    // 1. QKV projection: [8192,1024] @ [1024,3072]
    gemm_mma<true, false><<<dim3(24, 64, 1), 512, GEMM_SMEM>>>(
        s_v, 1024, 0, 0, W_qkv, 3072, 0, 0, p_qkv, 3072, 0, 1024, nullptr);
    // 2. QK projection: [8192,1024] @ [1024,2048]
    gemm_mma<true, false><<<dim3(16, 64, 1), 512, GEMM_SMEM>>>(
        s_m, 1024, 0, 0, W_qk, 2048, 0, 0, p_qk, 2048, 0, 1024, nullptr);
    // 3. m-stream scores: per (b,h)  S = q_m @ k_m^T, K=128 (B already [N,K])
    gemm_mma<false, false><<<dim3(8, 8, 64), 512, GEMM_SMEM>>>(
        p_qk, 2048, (size_t)NN * 2048, 128,
        p_qk + 1024, 2048, (size_t)NN * 2048, 128,
        p_sm, 1024, (size_t)NN * NN, 128, nullptr);
    // 4. inner-softmax row stats
    row_stats<<<64 * 1024, 256>>>();
    // 5. fused attention
    attn_kernel<<<dim3(16, NH, NB), 256, sizeof(AttnSmem)>>>(g_l);
    // 6. output projection + bias: [8192,1024] @ [1024,1024]
    gemm_mma<true, true><<<dim3(8, 64, 1), 512, GEMM_SMEM>>>(
        p_ao, 1024, 0, 0, W_out, 1024, 0, 0, out, 1024, 0, 1024, b_out);
}

// round 5
// speedup vs baseline: 1.7111x; 1.1441x over previous
#include <cuda_runtime.h>
#include <cuda_bf16.h>
#include <cstdint>
#include <math.h>

#define NB 8
#define NN 1024
#define NH 8
#define SCALE_F 0.08838834764831845f  // 128^-0.5

// ---------------- scratch (device globals; no cudaMalloc allowed) ----------
__device__ float g_qkv[8ull * 1024 * 3072];   // fp32 [b*n][3072] = q_v|k_v|v
__device__ float g_sm [64ull * 1024 * 1024];  // fp32 [b*h][i][j] raw m-scores
__device__ float g_mrow[64 * 1024];
__device__ float g_invl[64 * 1024];

// bf16 split planes (hi / lo)
__device__ __nv_bfloat16 g_svh[8ull * 1024 * 1024];     // s_v split
__device__ __nv_bfloat16 g_svl[8ull * 1024 * 1024];
__device__ __nv_bfloat16 g_smh_in[8ull * 1024 * 1024];  // s_m split
__device__ __nv_bfloat16 g_sml_in[8ull * 1024 * 1024];
__device__ __nv_bfloat16 g_wqkvh[3072ull * 1024];       // W_qkv^T [3072][1024]
__device__ __nv_bfloat16 g_wqkvl[3072ull * 1024];
__device__ __nv_bfloat16 g_wqkh[2048ull * 1024];        // W_qk^T [2048][1024]
__device__ __nv_bfloat16 g_wqkl[2048ull * 1024];
__device__ __nv_bfloat16 g_wouth[1024ull * 1024];       // W_out^T [1024][1024]
__device__ __nv_bfloat16 g_woutl[1024ull * 1024];
__device__ __nv_bfloat16 g_qkh[8ull * 1024 * 2048];     // q_m|k_m split (GEMM2 out)
__device__ __nv_bfloat16 g_qkl[8ull * 1024 * 2048];
__device__ __nv_bfloat16 g_aoh[8ull * 1024 * 1024];     // attn out split
__device__ __nv_bfloat16 g_aol[8ull * 1024 * 1024];

// ======================= helpers ===========================================
__device__ __forceinline__ uint32_t smem_u32(const void* p) {
    uint32_t a;
    asm("{ .reg .u64 t; cvta.to.shared.u64 t, %1; cvt.u32.u64 %0, t; }"
        : "=r"(a) : "l"(p));
    return a;
}
__device__ __forceinline__ void ldsm4(uint32_t* r, uint32_t addr) {
    asm volatile("ldmatrix.sync.aligned.m8n8.x4.shared.b16 {%0,%1,%2,%3}, [%4];"
                 : "=r"(r[0]), "=r"(r[1]), "=r"(r[2]), "=r"(r[3]) : "r"(addr));
}
__device__ __forceinline__ void mma16816(float* d, const uint32_t* a, const uint32_t* b) {
    asm volatile(
        "mma.sync.aligned.m16n8k16.row.col.f32.bf16.bf16.f32 "
        "{%0,%1,%2,%3}, {%4,%5,%6,%7}, {%8,%9}, {%0,%1,%2,%3};"
        : "+f"(d[0]), "+f"(d[1]), "+f"(d[2]), "+f"(d[3])
        : "r"(a[0]), "r"(a[1]), "r"(a[2]), "r"(a[3]), "r"(b[0]), "r"(b[1]));
}
__device__ __forceinline__ uint32_t sw_off(uint32_t off) {
    return off ^ ((off >> 3) & 0x70);
}
__device__ __forceinline__ uint32_t pack2(float a, float b) {
    __nv_bfloat162 t;
    t.x = __float2bfloat16(a);
    t.y = __float2bfloat16(b);
    return *(uint32_t*)&t;
}
__device__ __forceinline__ void split4(const float4& v, uint32_t& h01, uint32_t& h23,
                                       uint32_t& l01, uint32_t& l23) {
    __nv_bfloat16 b0 = __float2bfloat16(v.x);
    __nv_bfloat16 b1 = __float2bfloat16(v.y);
    __nv_bfloat16 b2 = __float2bfloat16(v.z);
    __nv_bfloat16 b3 = __float2bfloat16(v.w);
    __nv_bfloat162 h; h.x = b0; h.y = b1; h01 = *(uint32_t*)&h;
    h.x = b2; h.y = b3; h23 = *(uint32_t*)&h;
    l01 = pack2(v.x - __bfloat162float(b0), v.y - __bfloat162float(b1));
    l23 = pack2(v.z - __bfloat162float(b2), v.w - __bfloat162float(b3));
}

#define CP16(dst, src) \
    asm volatile("cp.async.cg.shared.global [%0], [%1], 16;" \
                 :: "r"(dst), "l"(__cvta_generic_to_global(src)))
#define CP_COMMIT() asm volatile("cp.async.commit_group;" ::: "memory")
#define CP_WAIT1()  asm volatile("cp.async.wait_group 1;" ::: "memory")

// ======================= conversion kernels ================================
// split fp32 activation -> hi/lo bf16 (same layout), float4 granular
__global__ __launch_bounds__(512) void asplit(const float4* __restrict__ in,
                                              uint2* __restrict__ oh,
                                              uint2* __restrict__ ol, int n4)
{
    for (int i = blockIdx.x * 512 + threadIdx.x; i < n4; i += gridDim.x * 512) {
        float4 v = in[i];
        uint32_t h01, h23, l01, l23;
        split4(v, h01, h23, l01, l23);
        oh[i] = make_uint2(h01, h23);
        ol[i] = make_uint2(l01, l23);
    }
}

// transpose + split weights: W [Kd][Nd] fp32 -> T [Nd][Kd] hi/lo bf16
__global__ __launch_bounds__(256) void wsplit_t(const float* __restrict__ W,
                                                int Kd, int Nd,
                                                __nv_bfloat16* __restrict__ Th,
                                                __nv_bfloat16* __restrict__ Tl)
{
    __shared__ float t[32][33];
    const int n0 = blockIdx.x * 32, k0 = blockIdx.y * 32;
    const int tx = threadIdx.x & 31, ty = threadIdx.x >> 5;  // 32 x 8
#pragma unroll
    for (int i = 0; i < 32; i += 8)
        t[ty + i][tx] = W[(size_t)(k0 + ty + i) * Nd + n0 + tx];
    __syncthreads();
#pragma unroll
    for (int i = 0; i < 32; i += 8) {
        float v = t[tx][ty + i];
        __nv_bfloat16 h = __float2bfloat16(v);
        __nv_bfloat16 l = __float2bfloat16(v - __bfloat162float(h));
        size_t o = (size_t)(n0 + ty + i) * Kd + k0 + tx;
        Th[o] = h;
        Tl[o] = l;
    }
}

// ======================= pipelined bf16 mma.sync GEMM ======================
// C[M,N] = A[M,K] * B^T[N,K]  (both operands K-major bf16 hi/lo planes)
// CTA 128x128, K-chunk 64, 512 thr (16 warps, 4x4 grid, 32x32/warp), 3 stages.
// EPI: 0 = fp32 C, 1 = fp32 C + bias, 2 = split bf16 C (Ch/Cl)
#define ST_BYTES  65536          // AH|AL|BH|BL, 16KB each, SW128 rows of 128B
#define NSTAGE    3
#define GEMM_SMEM (1024 + NSTAGE * ST_BYTES)

template<int EPI>
__global__ __launch_bounds__(512, 1) void gemm_bf16(
    const __nv_bfloat16* __restrict__ Ah, const __nv_bfloat16* __restrict__ Al,
    int lda, size_t Azb, size_t Azh,
    const __nv_bfloat16* __restrict__ Bh, const __nv_bfloat16* __restrict__ Bl,
    int ldb, size_t Bzb, size_t Bzh,
    float* __restrict__ C, __nv_bfloat16* __restrict__ Ch,
    __nv_bfloat16* __restrict__ Cl,
    int ldc, size_t Cz, int K, const float* __restrict__ bias)
{
    extern __shared__ char smraw[];
    uint32_t raw = smem_u32(smraw);
    char* sm = smraw + ((1024u - (raw & 1023u)) & 1023u);
    const uint32_t smb = smem_u32(sm);

    const int tid = threadIdx.x;
    const int wid = tid >> 5, lane = tid & 31;
    const int wm = wid & 3, wn = wid >> 2;
    const int bn = blockIdx.x * 128, bm = blockIdx.y * 128;
    const int z = blockIdx.z;

    const size_t zao = (size_t)(z >> 3) * Azb + (size_t)(z & 7) * Azh;
    const size_t zbo = (size_t)(z >> 3) * Bzb + (size_t)(z & 7) * Bzh;

    const __nv_bfloat16* pls[4] = {
        Ah + zao + (size_t)bm * lda, Al + zao + (size_t)bm * lda,
        Bh + zbo + (size_t)bn * ldb, Bl + zbo + (size_t)bn * ldb };

    const int nchunks = K >> 6;

    // per-thread copy geometry: plane = it>>1, cc = tid + (it&1)*512
    const int crow = (tid >> 3) | 0;  // recomputed per it below

#define ISSUE_STAGE(cc_) do {                                                  \
        int _c = (cc_);                                                        \
        if (_c < nchunks) {                                                    \
            uint32_t sb = smb + (uint32_t)(_c % NSTAGE) * ST_BYTES;            \
            int _k0 = _c << 6;                                                 \
            _Pragma("unroll")                                                  \
            for (int it = 0; it < 8; ++it) {                                   \
                int pl = it >> 1;                                              \
                int cidx = tid + (it & 1) * 512;                               \
                int row = cidx >> 3, c16 = cidx & 7;                           \
                int ld = (pl < 2) ? lda : ldb;                                 \
                const __nv_bfloat16* g = pls[pl] + (size_t)row * ld + _k0 + c16 * 8; \
                uint32_t d = sb + pl * 16384 + sw_off(row * 128 + c16 * 16);   \
                CP16(d, g);                                                    \
            }                                                                  \
        }                                                                      \
        CP_COMMIT();                                                           \
    } while (0)

    float acc[2][4][4];
#pragma unroll
    for (int mt = 0; mt < 2; mt++)
#pragma unroll
        for (int nt = 0; nt < 4; nt++)
#pragma unroll
            for (int i = 0; i < 4; i++) acc[mt][nt][i] = 0.f;

    ISSUE_STAGE(0);
    ISSUE_STAGE(1);

    const uint32_t arow0 = wm * 32 + (lane & 15);
    const uint32_t akhalf = (lane >> 4) * 16;
    const uint32_t bg = lane >> 3, br = lane & 7;
    const uint32_t brow0 = wn * 32 + (bg >> 1) * 8 + br;
    const uint32_t bkhalf = (bg & 1) * 16;

    for (int c = 0; c < nchunks; ++c) {
        CP_WAIT1();
        __syncthreads();
        ISSUE_STAGE(c + 2);

        const uint32_t so = smb + (uint32_t)(c % NSTAGE) * ST_BYTES;
        const uint32_t aHb = so, aLb = so + 16384;
        const uint32_t bHb = so + 32768, bLb = so + 49152;

#pragma unroll
        for (int k16 = 0; k16 < 4; ++k16) {
            const uint32_t kb = k16 * 32;
            uint32_t offA0 = sw_off(arow0 * 128 + kb + akhalf);
            uint32_t offA1 = sw_off((arow0 + 16) * 128 + kb + akhalf);
            uint32_t offB0 = sw_off(brow0 * 128 + kb + bkhalf);
            uint32_t offB1 = sw_off((brow0 + 16) * 128 + kb + bkhalf);

            uint32_t aH[2][4], aL[2][4];
            ldsm4(aH[0], aHb + offA0); ldsm4(aH[1], aHb + offA1);
            ldsm4(aL[0], aLb + offA0); ldsm4(aL[1], aLb + offA1);

            uint32_t bH01[4], bH23[4], bL01[4], bL23[4];
            ldsm4(bH01, bHb + offB0); ldsm4(bH23, bHb + offB1);
            ldsm4(bL01, bLb + offB0); ldsm4(bL23, bLb + offB1);

#pragma unroll
            for (int mt = 0; mt < 2; mt++) {
#pragma unroll
                for (int nt = 0; nt < 4; nt++) {
                    const uint32_t* bh = (nt < 2) ? &bH01[(nt & 1) * 2] : &bH23[(nt & 1) * 2];
                    const uint32_t* bl = (nt < 2) ? &bL01[(nt & 1) * 2] : &bL23[(nt & 1) * 2];
                    mma16816(acc[mt][nt], aH[mt], bh);
                    mma16816(acc[mt][nt], aH[mt], bl);
                    mma16816(acc[mt][nt], aL[mt], bh);
                }
            }
        }
        __syncthreads();
    }
#undef ISSUE_STAGE

    // ---- epilogue ----
    const int rgrp = lane >> 2, cpair = (lane & 3) * 2;
#pragma unroll
    for (int mt = 0; mt < 2; mt++) {
#pragma unroll
        for (int nt = 0; nt < 4; nt++) {
            int row0 = bm + wm * 32 + mt * 16 + rgrp;
            int col = bn + wn * 32 + nt * 8 + cpair;
            if (EPI == 2) {
                size_t o0 = (size_t)z * Cz + (size_t)row0 * ldc + col;
                size_t o1 = o0 + 8ull * ldc;
                float x0 = acc[mt][nt][0], x1 = acc[mt][nt][1];
                float x2 = acc[mt][nt][2], x3 = acc[mt][nt][3];
                __nv_bfloat16 h0 = __float2bfloat16(x0), h1 = __float2bfloat16(x1);
                __nv_bfloat16 h2 = __float2bfloat16(x2), h3 = __float2bfloat16(x3);
                *(uint32_t*)(Ch + o0) = pack2(x0, x1) , // hi pair
                *(uint32_t*)(Ch + o0) = ([&]{ __nv_bfloat162 t; t.x=h0; t.y=h1; return *(uint32_t*)&t; })();
                *(uint32_t*)(Ch + o1) = ([&]{ __nv_bfloat162 t; t.x=h2; t.y=h3; return *(uint32_t*)&t; })();
                *(uint32_t*)(Cl + o0) = pack2(x0 - __bfloat162float(h0), x1 - __bfloat162float(h1));
                *(uint32_t*)(Cl + o1) = pack2(x2 - __bfloat162float(h2), x3 - __bfloat162float(h3));
            } else {
                float b0 = 0.f, b1 = 0.f;
                if (EPI == 1) { b0 = bias[col]; b1 = bias[col + 1]; }
                float2 v0, v1;
                v0.x = acc[mt][nt][0] + b0; v0.y = acc[mt][nt][1] + b1;
                v1.x = acc[mt][nt][2] + b0; v1.y = acc[mt][nt][3] + b1;
                float* Cb = C + (size_t)z * Cz;
                *(float2*)(Cb + (size_t)row0 * ldc + col) = v0;
                *(float2*)(Cb + (size_t)(row0 + 8) * ldc + col) = v1;
            }
        }
    }
}

// ---------------- row stats: max and 1/sumexp ------------------------------
__global__ __launch_bounds__(256) void row_stats()
{
    const int row = blockIdx.x;
    const float4* p = (const float4*)(g_sm + (size_t)row * NN);
    const int tid = threadIdx.x;
    __shared__ float red8[8];
    __shared__ float bval;

    float4 v = p[tid];
    float m = fmaxf(fmaxf(v.x, v.y), fmaxf(v.z, v.w));
#pragma unroll
    for (int o = 16; o > 0; o >>= 1) m = fmaxf(m, __shfl_xor_sync(~0u, m, o));
    if ((tid & 31) == 0) red8[tid >> 5] = m;
    __syncthreads();
    if (tid == 0) {
        float t = red8[0];
#pragma unroll
        for (int i = 1; i < 8; ++i) t = fmaxf(t, red8[i]);
        bval = t;
    }
    __syncthreads();
    const float mv = bval;

    float s = __expf(v.x - mv) + __expf(v.y - mv) + __expf(v.z - mv) + __expf(v.w - mv);
#pragma unroll
    for (int o = 16; o > 0; o >>= 1) s += __shfl_xor_sync(~0u, s, o);
    if ((tid & 31) == 0) red8[tid >> 5] = s;
    __syncthreads();
    if (tid == 0) {
        float t = 0.f;
#pragma unroll
        for (int i = 0; i < 8; ++i) t += red8[i];
        g_mrow[row] = mv;
        g_invl[row] = 1.f / t;
    }
}

// ---------------- fused flash attention ------------------------------------
struct AttnSmem {
    float QvT[128][68];
    float KvT[128][68];
    float V[64][132];
    float P[64][68];
    float red[64][16];
    float mi[64], invli[64], mrun[64], lrun[64], alpha[64], mnew[64];
};

__global__ __launch_bounds__(256) void attn_kernel(const float* __restrict__ gl)
{
    extern __shared__ __align__(16) char smraw[];
    AttnSmem& s = *reinterpret_cast<AttnSmem*>(smraw);
    const int tid = threadIdx.x;
    const int tx = tid & 15, ty = tid >> 4;
    const int i0 = blockIdx.x * 64;
    const int h = blockIdx.y, b = blockIdx.z;
    const size_t bh = (size_t)(b * NH + h);

    const float* qv = g_qkv + (size_t)b * NN * 3072 + h * 128;
    const float* kv = g_qkv + (size_t)b * NN * 3072 + 1024 + h * 128;
    const float* vv = g_qkv + (size_t)b * NN * 3072 + 2048 + h * 128;
    const float* Sm = g_sm + bh * NN * NN;
    const float* GL = gl + bh * NN * NN;

#pragma unroll
    for (int it = 0; it < 8; it++) {
        int idx = tid + it * 256;
        int row = idx >> 5;
        int d4 = (idx & 31) << 2;
        float4 a = *(const float4*)(qv + (size_t)(i0 + row) * 3072 + d4);
        s.QvT[d4 + 0][row] = a.x; s.QvT[d4 + 1][row] = a.y;
        s.QvT[d4 + 2][row] = a.z; s.QvT[d4 + 3][row] = a.w;
    }
    if (tid < 64) {
        s.mi[tid]    = g_mrow[bh * NN + i0 + tid];
        s.invli[tid] = g_invl[bh * NN + i0 + tid];
        s.mrun[tid] = -1e30f;
        s.lrun[tid] = 0.f;
    }

    float O[4][8];
#pragma unroll
    for (int r = 0; r < 4; r++)
#pragma unroll
        for (int c = 0; c < 8; c++) O[r][c] = 0.f;

    const int srow = ty * 4, scol = tx * 4, ocol = tx * 8;

    for (int j0 = 0; j0 < NN; j0 += 64) {
        __syncthreads();
#pragma unroll
        for (int it = 0; it < 8; it++) {
            int idx = tid + it * 256;
            int row = idx >> 5;
            int d4 = (idx & 31) << 2;
            float4 a = *(const float4*)(kv + (size_t)(j0 + row) * 3072 + d4);
            s.KvT[d4 + 0][row] = a.x; s.KvT[d4 + 1][row] = a.y;
            s.KvT[d4 + 2][row] = a.z; s.KvT[d4 + 3][row] = a.w;
            float4 c = *(const float4*)(vv + (size_t)(j0 + row) * 3072 + d4);
            *(float4*)&s.V[row][d4] = c;
        }
        float smv[4][4], glv[4][4];
#pragma unroll
        for (int r = 0; r < 4; r++) {
            float4 t0 = *(const float4*)(Sm + (size_t)(i0 + srow + r) * NN + j0 + scol);
            smv[r][0] = t0.x; smv[r][1] = t0.y; smv[r][2] = t0.z; smv[r][3] = t0.w;
            float4 t1 = *(const float4*)(GL + (size_t)(i0 + srow + r) * NN + j0 + scol);
            glv[r][0] = t1.x; glv[r][1] = t1.y; glv[r][2] = t1.z; glv[r][3] = t1.w;
        }
        __syncthreads();

        float sv[4][4];
#pragma unroll
        for (int r = 0; r < 4; r++)
#pragma unroll
            for (int c = 0; c < 4; c++) sv[r][c] = 0.f;
#pragma unroll 4
        for (int d = 0; d < 128; d++) {
            float4 q4 = *(const float4*)&s.QvT[d][srow];
            float4 k4 = *(const float4*)&s.KvT[d][scol];
            float qa[4] = {q4.x, q4.y, q4.z, q4.w};
            float ka[4] = {k4.x, k4.y, k4.z, k4.w};
#pragma unroll
            for (int r = 0; r < 4; r++)
#pragma unroll
                for (int c = 0; c < 4; c++)
                    sv[r][c] = fmaf(qa[r], ka[c], sv[r][c]);
        }

        float dv[4][4];
#pragma unroll
        for (int r = 0; r < 4; r++) {
            float mi_r = s.mi[srow + r], il_r = s.invli[srow + r];
            float rmax = -1e30f;
#pragma unroll
            for (int c = 0; c < 4; c++) {
                float pm = __expf(smv[r][c] - mi_r) * il_r;
                float d = fmaf(pm * sv[r][c], SCALE_F, glv[r][c]);
                dv[r][c] = d;
                rmax = fmaxf(rmax, d);
            }
            s.red[srow + r][tx] = rmax;
        }
        __syncthreads();
        if (tid < 64) {
            float tm = -1e30f;
#pragma unroll
            for (int t = 0; t < 16; t++) tm = fmaxf(tm, s.red[tid][t]);
            float mo = s.mrun[tid];
            float mn = fmaxf(mo, tm);
            s.mnew[tid] = mn;
            s.alpha[tid] = __expf(mo - mn);
            s.mrun[tid] = mn;
        }
        __syncthreads();
#pragma unroll
        for (int r = 0; r < 4; r++) {
            float mn = s.mnew[srow + r];
            float4 pw;
            float p0 = __expf(dv[r][0] - mn);
            float p1 = __expf(dv[r][1] - mn);
            float p2 = __expf(dv[r][2] - mn);
            float p3 = __expf(dv[r][3] - mn);
            pw.x = p0; pw.y = p1; pw.z = p2; pw.w = p3;
            *(float4*)&s.P[srow + r][scol] = pw;
            s.red[srow + r][tx] = p0 + p1 + p2 + p3;
            float al = s.alpha[srow + r];
#pragma unroll
            for (int c = 0; c < 8; c++) O[r][c] *= al;
        }
        __syncthreads();
        if (tid < 64) {
            float ssum = 0.f;
#pragma unroll
            for (int t = 0; t < 16; t++) ssum += s.red[tid][t];
            s.lrun[tid] = s.lrun[tid] * s.alpha[tid] + ssum;
        }
        for (int k4 = 0; k4 < 64; k4 += 4) {
            float pr[4][4];
#pragma unroll
            for (int r = 0; r < 4; r++) {
                float4 t = *(const float4*)&s.P[srow + r][k4];
                pr[r][0] = t.x; pr[r][1] = t.y; pr[r][2] = t.z; pr[r][3] = t.w;
            }
#pragma unroll
            for (int kk = 0; kk < 4; kk++) {
                float4 v0 = *(const float4*)&s.V[k4 + kk][ocol];
                float4 v1 = *(const float4*)&s.V[k4 + kk][ocol + 4];
                float vb[8] = {v0.x, v0.y, v0.z, v0.w, v1.x, v1.y, v1.z, v1.w};
#pragma unroll
                for (int r = 0; r < 4; r++)
#pragma unroll
                    for (int c = 0; c < 8; c++)
                        O[r][c] = fmaf(pr[r][kk], vb[c], O[r][c]);
            }
        }
    }
    __syncthreads();
    // epilogue: write split bf16 planes for the output GEMM
#pragma unroll
    for (int r = 0; r < 4; r++) {
        float inv = 1.f / s.lrun[srow + r];
        float o[8];
#pragma unroll
        for (int c = 0; c < 8; c++) o[c] = O[r][c] * inv;
        uint32_t hp[4], lp[4];
#pragma unroll
        for (int c = 0; c < 4; c++) {
            __nv_bfloat16 h0 = __float2bfloat16(o[2 * c]);
            __nv_bfloat16 h1 = __float2bfloat16(o[2 * c + 1]);
            __nv_bfloat162 t; t.x = h0; t.y = h1;
            hp[c] = *(uint32_t*)&t;
            lp[c] = pack2(o[2 * c] - __bfloat162float(h0),
                          o[2 * c + 1] - __bfloat162float(h1));
        }
        size_t off = (size_t)(b * NN + i0 + srow + r) * 1024 + h * 128 + ocol;
        *(uint4*)(g_aoh + off) = make_uint4(hp[0], hp[1], hp[2], hp[3]);
        *(uint4*)(g_aol + off) = make_uint4(lp[0], lp[1], lp[2], lp[3]);
    }
}

// ---------------- launch ----------------------------------------------------
extern "C" void kernel_launch(void* const* d_in, const int* in_sizes, int n_in,
                              void* d_out, int out_size)
{
    const float* s_v   = (const float*)d_in[0];
    const float* s_m   = (const float*)d_in[1];
    const float* g_l   = (const float*)d_in[2];
    const float* W_qkv = (const float*)d_in[3];
    const float* W_qk  = (const float*)d_in[4];
    const float* W_out = (const float*)d_in[5];
    const float* b_out = (const float*)d_in[6];
    float* out = (float*)d_out;

    float *p_qkv, *p_sm;
    __nv_bfloat16 *p_svh, *p_svl, *p_smh, *p_sml;
    __nv_bfloat16 *p_wqkvh, *p_wqkvl, *p_wqkh, *p_wqkl, *p_wouth, *p_woutl;
    __nv_bfloat16 *p_qkh, *p_qkl, *p_aoh, *p_aol;
    cudaGetSymbolAddress((void**)&p_qkv, g_qkv);
    cudaGetSymbolAddress((void**)&p_sm,  g_sm);
    cudaGetSymbolAddress((void**)&p_svh, g_svh);
    cudaGetSymbolAddress((void**)&p_svl, g_svl);
    cudaGetSymbolAddress((void**)&p_smh, g_smh_in);
    cudaGetSymbolAddress((void**)&p_sml, g_sml_in);
    cudaGetSymbolAddress((void**)&p_wqkvh, g_wqkvh);
    cudaGetSymbolAddress((void**)&p_wqkvl, g_wqkvl);
    cudaGetSymbolAddress((void**)&p_wqkh, g_wqkh);
    cudaGetSymbolAddress((void**)&p_wqkl, g_wqkl);
    cudaGetSymbolAddress((void**)&p_wouth, g_wouth);
    cudaGetSymbolAddress((void**)&p_woutl, g_woutl);
    cudaGetSymbolAddress((void**)&p_qkh, g_qkh);
    cudaGetSymbolAddress((void**)&p_qkl, g_qkl);
    cudaGetSymbolAddress((void**)&p_aoh, g_aoh);
    cudaGetSymbolAddress((void**)&p_aol, g_aol);

    cudaFuncSetAttribute(gemm_bf16<0>, cudaFuncAttributeMaxDynamicSharedMemorySize, GEMM_SMEM);
    cudaFuncSetAttribute(gemm_bf16<1>, cudaFuncAttributeMaxDynamicSharedMemorySize, GEMM_SMEM);
    cudaFuncSetAttribute(gemm_bf16<2>, cudaFuncAttributeMaxDynamicSharedMemorySize, GEMM_SMEM);
    cudaFuncSetAttribute(attn_kernel, cudaFuncAttributeMaxDynamicSharedMemorySize,
                         (int)sizeof(AttnSmem));

    // 0. conversions
    asplit<<<2048, 512>>>((const float4*)s_v, (uint2*)p_svh, (uint2*)p_svl, 8 * 1024 * 1024 / 4);
    asplit<<<2048, 512>>>((const float4*)s_m, (uint2*)p_smh, (uint2*)p_sml, 8 * 1024 * 1024 / 4);
    wsplit_t<<<dim3(96, 32), 256>>>(W_qkv, 1024, 3072, p_wqkvh, p_wqkvl);
    wsplit_t<<<dim3(64, 32), 256>>>(W_qk, 1024, 2048, p_wqkh, p_wqkl);
    wsplit_t<<<dim3(32, 32), 256>>>(W_out, 1024, 1024, p_wouth, p_woutl);

    // 1. QKV projection -> fp32 g_qkv
    gemm_bf16<0><<<dim3(24, 64, 1), 512, GEMM_SMEM>>>(
        p_svh, p_svl, 1024, 0, 0, p_wqkvh, p_wqkvl, 1024, 0, 0,
        p_qkv, nullptr, nullptr, 3072, 0, 1024, nullptr);
    // 2. QK projection -> split bf16 g_qkh/g_qkl
    gemm_bf16<2><<<dim3(16, 64, 1), 512, GEMM_SMEM>>>(
        p_smh, p_sml, 1024, 0, 0, p_wqkh, p_wqkl, 1024, 0, 0,
        nullptr, p_qkh, p_qkl, 2048, 0, 1024, nullptr);
    // 3. m-stream scores per (b,h): S = q_m @ k_m^T (K=128) -> fp32 g_sm
    gemm_bf16<0><<<dim3(8, 8, 64), 512, GEMM_SMEM>>>(
        p_qkh, p_qkl, 2048, (size_t)NN * 2048, 128,
        p_qkh + 1024, p_qkl + 1024, 2048, (size_t)NN * 2048, 128,
        p_sm, nullptr, nullptr, 1024, (size_t)NN * NN, 128, nullptr);
    // 4. inner-softmax row stats
    row_stats<<<64 * 1024, 256>>>();
    // 5. fused attention -> split bf16 g_aoh/g_aol
    attn_kernel<<<dim3(16, NH, NB), 256, sizeof(AttnSmem)>>>(g_l);
    // 6. output projection + bias -> out
    gemm_bf16<1><<<dim3(8, 64, 1), 512, GEMM_SMEM>>>(
        p_aoh, p_aol, 1024, 0, 0, p_wouth, p_woutl, 1024, 0, 0,
        out, nullptr, nullptr, 1024, 0, 1024, b_out);
}

// round 6
// speedup vs baseline: 2.9798x; 1.7415x over previous
#include <cuda_runtime.h>
#include <cuda_bf16.h>
#include <cstdint>
#include <math.h>

#define NB 8
#define NN 1024
#define NH 8
#define SCALE_F 0.08838834764831845f  // 128^-0.5

// ---------------- scratch (device globals; no cudaMalloc allowed) ----------
__device__ float g_sm [64ull * 1024 * 1024];  // fp32 [b*h][i][j] raw m-scores
__device__ float g_mrow[64 * 1024];
__device__ float g_invl[64 * 1024];

// bf16 split planes (hi / lo)
__device__ __nv_bfloat16 g_svh[8ull * 1024 * 1024];     // s_v split
__device__ __nv_bfloat16 g_svl[8ull * 1024 * 1024];
__device__ __nv_bfloat16 g_smh_in[8ull * 1024 * 1024];  // s_m split
__device__ __nv_bfloat16 g_sml_in[8ull * 1024 * 1024];
__device__ __nv_bfloat16 g_wqkvh[3072ull * 1024];       // W_qkv^T
__device__ __nv_bfloat16 g_wqkvl[3072ull * 1024];
__device__ __nv_bfloat16 g_wqkh[2048ull * 1024];        // W_qk^T
__device__ __nv_bfloat16 g_wqkl[2048ull * 1024];
__device__ __nv_bfloat16 g_wouth[1024ull * 1024];       // W_out^T
__device__ __nv_bfloat16 g_woutl[1024ull * 1024];
__device__ __nv_bfloat16 g_qkh[8ull * 1024 * 2048];     // q_m|k_m split
__device__ __nv_bfloat16 g_qkl[8ull * 1024 * 2048];
__device__ __nv_bfloat16 g_avh[8ull * 1024 * 2048];     // q_v|k_v split
__device__ __nv_bfloat16 g_avl[8ull * 1024 * 2048];
__device__ __nv_bfloat16 g_vth[64ull * 128 * 1024];     // v transposed [bh][d][n]
__device__ __nv_bfloat16 g_vtl[64ull * 128 * 1024];
__device__ __nv_bfloat16 g_aoh[8ull * 1024 * 1024];     // attn out split
__device__ __nv_bfloat16 g_aol[8ull * 1024 * 1024];

// ======================= helpers ===========================================
__device__ __forceinline__ uint32_t smem_u32(const void* p) {
    uint32_t a;
    asm("{ .reg .u64 t; cvta.to.shared.u64 t, %1; cvt.u32.u64 %0, t; }"
        : "=r"(a) : "l"(p));
    return a;
}
__device__ __forceinline__ void ldsm4(uint32_t* r, uint32_t addr) {
    asm volatile("ldmatrix.sync.aligned.m8n8.x4.shared.b16 {%0,%1,%2,%3}, [%4];"
                 : "=r"(r[0]), "=r"(r[1]), "=r"(r[2]), "=r"(r[3]) : "r"(addr));
}
__device__ __forceinline__ void mma16816(float* d, const uint32_t* a, const uint32_t* b) {
    asm volatile(
        "mma.sync.aligned.m16n8k16.row.col.f32.bf16.bf16.f32 "
        "{%0,%1,%2,%3}, {%4,%5,%6,%7}, {%8,%9}, {%0,%1,%2,%3};"
        : "+f"(d[0]), "+f"(d[1]), "+f"(d[2]), "+f"(d[3])
        : "r"(a[0]), "r"(a[1]), "r"(a[2]), "r"(a[3]), "r"(b[0]), "r"(b[1]));
}
__device__ __forceinline__ uint32_t sw_off(uint32_t off) {
    return off ^ ((off >> 3) & 0x70);
}
__device__ __forceinline__ uint32_t pack2(float a, float b) {
    __nv_bfloat162 t;
    t.x = __float2bfloat16(a);
    t.y = __float2bfloat16(b);
    return *(uint32_t*)&t;
}
__device__ __forceinline__ void packPair(float a, float b, uint32_t& hi, uint32_t& lo) {
    __nv_bfloat16 h0 = __float2bfloat16(a), h1 = __float2bfloat16(b);
    __nv_bfloat162 t; t.x = h0; t.y = h1;
    hi = *(uint32_t*)&t;
    lo = pack2(a - __bfloat162float(h0), b - __bfloat162float(h1));
}
__device__ __forceinline__ void split4(const float4& v, uint32_t& h01, uint32_t& h23,
                                       uint32_t& l01, uint32_t& l23) {
    packPair(v.x, v.y, h01, l01);
    packPair(v.z, v.w, h23, l23);
}

#define CP16(dst, src) \
    asm volatile("cp.async.cg.shared.global [%0], [%1], 16;" \
                 :: "r"(dst), "l"(__cvta_generic_to_global(src)))
#define CP_COMMIT() asm volatile("cp.async.commit_group;" ::: "memory")
#define CP_WAIT1()  asm volatile("cp.async.wait_group 1;" ::: "memory")
#define CP_WAIT0()  asm volatile("cp.async.wait_group 0;" ::: "memory")

// ======================= conversion kernels ================================
__global__ __launch_bounds__(512) void asplit(const float4* __restrict__ in,
                                              uint2* __restrict__ oh,
                                              uint2* __restrict__ ol, int n4)
{
    for (int i = blockIdx.x * 512 + threadIdx.x; i < n4; i += gridDim.x * 512) {
        float4 v = in[i];
        uint32_t h01, h23, l01, l23;
        split4(v, h01, h23, l01, l23);
        oh[i] = make_uint2(h01, h23);
        ol[i] = make_uint2(l01, l23);
    }
}

__global__ __launch_bounds__(256) void wsplit_t(const float* __restrict__ W,
                                                int Kd, int Nd,
                                                __nv_bfloat16* __restrict__ Th,
                                                __nv_bfloat16* __restrict__ Tl)
{
    __shared__ float t[32][33];
    const int n0 = blockIdx.x * 32, k0 = blockIdx.y * 32;
    const int tx = threadIdx.x & 31, ty = threadIdx.x >> 5;
#pragma unroll
    for (int i = 0; i < 32; i += 8)
        t[ty + i][tx] = W[(size_t)(k0 + ty + i) * Nd + n0 + tx];
    __syncthreads();
#pragma unroll
    for (int i = 0; i < 32; i += 8) {
        float v = t[tx][ty + i];
        __nv_bfloat16 h = __float2bfloat16(v);
        __nv_bfloat16 l = __float2bfloat16(v - __bfloat162float(h));
        size_t o = (size_t)(n0 + ty + i) * Kd + k0 + tx;
        Th[o] = h;
        Tl[o] = l;
    }
}

// ======================= pipelined bf16 mma.sync GEMM ======================
// EPI: 0 fp32 C; 1 fp32 C + bias; 2 split bf16 Ch/Cl; 3 qkv-special
#define ST_BYTES  65536
#define NSTAGE    3
#define GEMM_SMEM (1024 + NSTAGE * ST_BYTES)

template<int EPI>
__global__ __launch_bounds__(512, 1) void gemm_bf16(
    const __nv_bfloat16* __restrict__ Ah, const __nv_bfloat16* __restrict__ Al,
    int lda, size_t Azb, size_t Azh,
    const __nv_bfloat16* __restrict__ Bh, const __nv_bfloat16* __restrict__ Bl,
    int ldb, size_t Bzb, size_t Bzh,
    float* __restrict__ C, __nv_bfloat16* __restrict__ Ch,
    __nv_bfloat16* __restrict__ Cl,
    int ldc, size_t Cz, int K, const float* __restrict__ bias)
{
    extern __shared__ char smraw[];
    uint32_t raw = smem_u32(smraw);
    char* sm = smraw + ((1024u - (raw & 1023u)) & 1023u);
    const uint32_t smb = smem_u32(sm);

    const int tid = threadIdx.x;
    const int wid = tid >> 5, lane = tid & 31;
    const int wm = wid & 3, wn = wid >> 2;
    const int bn = blockIdx.x * 128, bm = blockIdx.y * 128;
    const int z = blockIdx.z;

    const size_t zao = (size_t)(z >> 3) * Azb + (size_t)(z & 7) * Azh;
    const size_t zbo = (size_t)(z >> 3) * Bzb + (size_t)(z & 7) * Bzh;

    const __nv_bfloat16* pls[4] = {
        Ah + zao + (size_t)bm * lda, Al + zao + (size_t)bm * lda,
        Bh + zbo + (size_t)bn * ldb, Bl + zbo + (size_t)bn * ldb };

    const int nchunks = K >> 6;

#define ISSUE_STAGE(cc_) do {                                                  \
        int _c = (cc_);                                                        \
        if (_c < nchunks) {                                                    \
            uint32_t sb = smb + (uint32_t)(_c % NSTAGE) * ST_BYTES;            \
            int _k0 = _c << 6;                                                 \
            _Pragma("unroll")                                                  \
            for (int it = 0; it < 8; ++it) {                                   \
                int pl = it >> 1;                                              \
                int cidx = tid + (it & 1) * 512;                               \
                int row = cidx >> 3, c16 = cidx & 7;                           \
                int ld = (pl < 2) ? lda : ldb;                                 \
                const __nv_bfloat16* g = pls[pl] + (size_t)row * ld + _k0 + c16 * 8; \
                uint32_t d = sb + pl * 16384 + sw_off(row * 128 + c16 * 16);   \
                CP16(d, g);                                                    \
            }                                                                  \
        }                                                                      \
        CP_COMMIT();                                                           \
    } while (0)

    float acc[2][4][4];
#pragma unroll
    for (int mt = 0; mt < 2; mt++)
#pragma unroll
        for (int nt = 0; nt < 4; nt++)
#pragma unroll
            for (int i = 0; i < 4; i++) acc[mt][nt][i] = 0.f;

    ISSUE_STAGE(0);
    ISSUE_STAGE(1);

    const uint32_t arow0 = wm * 32 + (lane & 15);
    const uint32_t akhalf = (lane >> 4) * 16;
    const uint32_t bg = lane >> 3, br = lane & 7;
    const uint32_t brow0 = wn * 32 + (bg >> 1) * 8 + br;
    const uint32_t bkhalf = (bg & 1) * 16;

    for (int c = 0; c < nchunks; ++c) {
        CP_WAIT1();
        __syncthreads();
        ISSUE_STAGE(c + 2);

        const uint32_t so = smb + (uint32_t)(c % NSTAGE) * ST_BYTES;
        const uint32_t aHb = so, aLb = so + 16384;
        const uint32_t bHb = so + 32768, bLb = so + 49152;

#pragma unroll
        for (int k16 = 0; k16 < 4; ++k16) {
            const uint32_t kb = k16 * 32;
            uint32_t offA0 = sw_off(arow0 * 128 + kb + akhalf);
            uint32_t offA1 = sw_off((arow0 + 16) * 128 + kb + akhalf);
            uint32_t offB0 = sw_off(brow0 * 128 + kb + bkhalf);
            uint32_t offB1 = sw_off((brow0 + 16) * 128 + kb + bkhalf);

            uint32_t aH[2][4], aL[2][4];
            ldsm4(aH[0], aHb + offA0); ldsm4(aH[1], aHb + offA1);
            ldsm4(aL[0], aLb + offA0); ldsm4(aL[1], aLb + offA1);

            uint32_t bH01[4], bH23[4], bL01[4], bL23[4];
            ldsm4(bH01, bHb + offB0); ldsm4(bH23, bHb + offB1);
            ldsm4(bL01, bLb + offB0); ldsm4(bL23, bLb + offB1);

#pragma unroll
            for (int mt = 0; mt < 2; mt++) {
#pragma unroll
                for (int nt = 0; nt < 4; nt++) {
                    const uint32_t* bh = (nt < 2) ? &bH01[(nt & 1) * 2] : &bH23[(nt & 1) * 2];
                    const uint32_t* bl = (nt < 2) ? &bL01[(nt & 1) * 2] : &bL23[(nt & 1) * 2];
                    mma16816(acc[mt][nt], aH[mt], bh);
                    mma16816(acc[mt][nt], aH[mt], bl);
                    mma16816(acc[mt][nt], aL[mt], bh);
                }
            }
        }
        __syncthreads();
    }
#undef ISSUE_STAGE

    const int rgrp = lane >> 2, cpair = (lane & 3) * 2;
#pragma unroll
    for (int mt = 0; mt < 2; mt++) {
#pragma unroll
        for (int nt = 0; nt < 4; nt++) {
            int row0 = bm + wm * 32 + mt * 16 + rgrp;
            int col = bn + wn * 32 + nt * 8 + cpair;
            float x0 = acc[mt][nt][0], x1 = acc[mt][nt][1];
            float x2 = acc[mt][nt][2], x3 = acc[mt][nt][3];
            if (EPI == 3) {
                if (col < 2048) {
                    size_t o0 = (size_t)row0 * 2048 + col;
                    size_t o1 = o0 + 8ull * 2048;
                    uint32_t hh, ll;
                    packPair(x0, x1, hh, ll);
                    *(uint32_t*)(g_avh + o0) = hh; *(uint32_t*)(g_avl + o0) = ll;
                    packPair(x2, x3, hh, ll);
                    *(uint32_t*)(g_avh + o1) = hh; *(uint32_t*)(g_avl + o1) = ll;
                } else {
                    int hh_ = (col - 2048) >> 7, d = (col - 2048) & 127;
                    int bb = row0 >> 10, nn = row0 & 1023;
                    size_t base = ((size_t)(bb * 8 + hh_) * 128 + d) * 1024 + nn;
                    __nv_bfloat16 h0 = __float2bfloat16(x0);
                    __nv_bfloat16 h1 = __float2bfloat16(x1);
                    __nv_bfloat16 h2 = __float2bfloat16(x2);
                    __nv_bfloat16 h3 = __float2bfloat16(x3);
                    g_vth[base] = h0;            g_vth[base + 1024] = h1;
                    g_vth[base + 8] = h2;        g_vth[base + 1024 + 8] = h3;
                    g_vtl[base] = __float2bfloat16(x0 - __bfloat162float(h0));
                    g_vtl[base + 1024] = __float2bfloat16(x1 - __bfloat162float(h1));
                    g_vtl[base + 8] = __float2bfloat16(x2 - __bfloat162float(h2));
                    g_vtl[base + 1024 + 8] = __float2bfloat16(x3 - __bfloat162float(h3));
                }
            } else if (EPI == 2) {
                size_t o0 = (size_t)z * Cz + (size_t)row0 * ldc + col;
                size_t o1 = o0 + 8ull * ldc;
                uint32_t hh, ll;
                packPair(x0, x1, hh, ll);
                *(uint32_t*)(Ch + o0) = hh; *(uint32_t*)(Cl + o0) = ll;
                packPair(x2, x3, hh, ll);
                *(uint32_t*)(Ch + o1) = hh; *(uint32_t*)(Cl + o1) = ll;
            } else {
                float b0 = 0.f, b1 = 0.f;
                if (EPI == 1) { b0 = bias[col]; b1 = bias[col + 1]; }
                float2 v0, v1;
                v0.x = x0 + b0; v0.y = x1 + b1;
                v1.x = x2 + b0; v1.y = x3 + b1;
                float* Cb = C + (size_t)z * Cz;
                *(float2*)(Cb + (size_t)row0 * ldc + col) = v0;
                *(float2*)(Cb + (size_t)(row0 + 8) * ldc + col) = v1;
            }
        }
    }
}

// ---------------- row stats ------------------------------------------------
__global__ __launch_bounds__(256) void row_stats()
{
    const int row = blockIdx.x;
    const float4* p = (const float4*)(g_sm + (size_t)row * NN);
    const int tid = threadIdx.x;
    __shared__ float red8[8];
    __shared__ float bval;

    float4 v = p[tid];
    float m = fmaxf(fmaxf(v.x, v.y), fmaxf(v.z, v.w));
#pragma unroll
    for (int o = 16; o > 0; o >>= 1) m = fmaxf(m, __shfl_xor_sync(~0u, m, o));
    if ((tid & 31) == 0) red8[tid >> 5] = m;
    __syncthreads();
    if (tid == 0) {
        float t = red8[0];
#pragma unroll
        for (int i = 1; i < 8; ++i) t = fmaxf(t, red8[i]);
        bval = t;
    }
    __syncthreads();
    const float mv = bval;

    float s = __expf(v.x - mv) + __expf(v.y - mv) + __expf(v.z - mv) + __expf(v.w - mv);
#pragma unroll
    for (int o = 16; o > 0; o >>= 1) s += __shfl_xor_sync(~0u, s, o);
    if ((tid & 31) == 0) red8[tid >> 5] = s;
    __syncthreads();
    if (tid == 0) {
        float t = 0.f;
#pragma unroll
        for (int i = 0; i < 8; ++i) t += red8[i];
        g_mrow[row] = mv;
        g_invl[row] = 1.f / t;
    }
}

// ================= tensor-core fused flash attention =======================
// CTA: 64 queries x head x batch, 256 threads (8 warps: 4 along m x 2 along j)
// smem: Q planes 32KB | K 2x32KB | Vt 2x32KB | red 2KB; O-reduce aliases K.
#define Q_OFF(hl, kc)      ((uint32_t)(((hl) * 2 + (kc)) * 8192))
#define K_OFF(buf, hl, kc) ((uint32_t)(32768 + (buf) * 32768 + ((hl) * 2 + (kc)) * 8192))
#define V_OFF(buf, hl)     ((uint32_t)(98304 + (buf) * 32768 + (hl) * 16384))
#define REDM_OFF 163840
#define REDS_OFF 164864
#define ATTN_SMEM (1024 + 165888)

__global__ __launch_bounds__(256, 1) void attn_mma(const float* __restrict__ gl)
{
    extern __shared__ char smraw[];
    uint32_t raw = smem_u32(smraw);
    char* sm = smraw + ((1024u - (raw & 1023u)) & 1023u);
    const uint32_t smb = smem_u32(sm);
    float* redm = (float*)(sm + REDM_OFF);
    float* reds = (float*)(sm + REDS_OFF);

    const int tid = threadIdx.x, lane = tid & 31, wid = tid >> 5;
    const int wm = wid & 3, wn = wid >> 2;
    const int bg = lane >> 3, br = lane & 7;
    const int i0 = blockIdx.x * 64, h = blockIdx.y, b = blockIdx.z;
    const int bh = b * 8 + h;

    const __nv_bfloat16* qsrc[2] = {
        g_avh + (size_t)(b * 1024 + i0) * 2048 + h * 128,
        g_avl + (size_t)(b * 1024 + i0) * 2048 + h * 128 };
    const __nv_bfloat16* ksrc[2] = {
        g_avh + (size_t)(b * 1024) * 2048 + 1024 + h * 128,
        g_avl + (size_t)(b * 1024) * 2048 + 1024 + h * 128 };
    const __nv_bfloat16* vsrc[2] = {
        g_vth + (size_t)bh * 128 * 1024,
        g_vtl + (size_t)bh * 128 * 1024 };
    const float* Sm = g_sm + ((size_t)bh << 20);
    const float* GL = gl + ((size_t)bh << 20);

#define ISSUE_KV(j0_, buf_) do {                                               \
        _Pragma("unroll")                                                      \
        for (int i = 0; i < 8; ++i) {                                          \
            int c = tid + i * 256;                                             \
            int hl = c >> 10, rem = c & 1023;                                  \
            int row = rem >> 4, seg = rem & 15;                                \
            CP16(smb + K_OFF(buf_, hl, seg >> 3) + sw_off(row * 128 + (seg & 7) * 16), \
                 ksrc[hl] + (size_t)((j0_) + row) * 2048 + seg * 8);           \
        }                                                                      \
        _Pragma("unroll")                                                      \
        for (int i = 0; i < 8; ++i) {                                          \
            int c = tid + i * 256;                                             \
            int hl = c >> 10, rem = c & 1023;                                  \
            int row = rem >> 3, seg = rem & 7;                                 \
            CP16(smb + V_OFF(buf_, hl) + sw_off(row * 128 + seg * 16),         \
                 vsrc[hl] + (size_t)row * 1024 + (j0_) + seg * 8);             \
        }                                                                      \
    } while (0)

    // Q load + KV tile 0 (group 0)
#pragma unroll
    for (int i = 0; i < 8; ++i) {
        int c = tid + i * 256;
        int hl = c >> 10, rem = c & 1023;
        int row = rem >> 4, seg = rem & 15;
        CP16(smb + Q_OFF(hl, seg >> 3) + sw_off(row * 128 + (seg & 7) * 16),
             qsrc[hl] + (size_t)row * 2048 + seg * 8);
    }
    ISSUE_KV(0, 0);
    CP_COMMIT();

    const int r0 = wm * 16 + (lane >> 2);
    const float mi0 = g_mrow[bh * 1024 + i0 + r0];
    const float mi1 = g_mrow[bh * 1024 + i0 + r0 + 8];
    const float il0 = g_invl[bh * 1024 + i0 + r0];
    const float il1 = g_invl[bh * 1024 + i0 + r0 + 8];

    float O[16][4];
#pragma unroll
    for (int g = 0; g < 16; g++)
#pragma unroll
        for (int i = 0; i < 4; i++) O[g][i] = 0.f;
    float m_run0 = -1e30f, m_run1 = -1e30f, l_run0 = 0.f, l_run1 = 0.f;
    float al0 = 0.f, al1 = 0.f;

    const uint32_t aRow = (uint32_t)(wm * 16 + (lane & 15)) * 128 + (lane >> 4) * 16;
    const uint32_t bRow0 = (uint32_t)(wn * 32 + (bg >> 1) * 8 + br) * 128 + (bg & 1) * 16;
    const uint32_t bRow1 = bRow0 + 16 * 128;

    for (int jt = 0; jt < 16; ++jt) {
        const int j0 = jt * 64, buf = jt & 1, par = jt & 1;
        CP_WAIT0();
        __syncthreads();
        if (jt < 15) { ISSUE_KV(j0 + 64, buf ^ 1); CP_COMMIT(); }

        // deferred l update (reds of previous tile now visible)
        if (jt > 0) {
            int pp = par ^ 1;
            l_run0 = l_run0 * al0 + reds[pp * 128 + r0 * 2] + reds[pp * 128 + r0 * 2 + 1];
            l_run1 = l_run1 * al1 + reds[pp * 128 + (r0 + 8) * 2] + reds[pp * 128 + (r0 + 8) * 2 + 1];
        }

        // prefetch S_m / g_l fragments
        const int colb = j0 + wn * 32 + (lane & 3) * 2;
        float2 smv[4][2], glv[4][2];
#pragma unroll
        for (int nt = 0; nt < 4; nt++) {
            smv[nt][0] = *(const float2*)(Sm + (size_t)(i0 + r0) * 1024 + colb + nt * 8);
            smv[nt][1] = *(const float2*)(Sm + (size_t)(i0 + r0 + 8) * 1024 + colb + nt * 8);
            glv[nt][0] = *(const float2*)(GL + (size_t)(i0 + r0) * 1024 + colb + nt * 8);
            glv[nt][1] = *(const float2*)(GL + (size_t)(i0 + r0 + 8) * 1024 + colb + nt * 8);
        }

        // ---- scores: S = Qh*Kh + Qh*Kl + Ql*Kh ----
        float sc[4][4];
#pragma unroll
        for (int nt = 0; nt < 4; nt++)
#pragma unroll
            for (int i = 0; i < 4; i++) sc[nt][i] = 0.f;

#pragma unroll
        for (int s = 0; s < 8; ++s) {
            const int kc = s >> 2;
            const uint32_t kb = (uint32_t)(s & 3) * 32;
            uint32_t aH[4], aL[4];
            ldsm4(aH, smb + Q_OFF(0, kc) + sw_off(aRow + kb));
            ldsm4(aL, smb + Q_OFF(1, kc) + sw_off(aRow + kb));
            uint32_t kh01[4], kh23[4], kl01[4], kl23[4];
            ldsm4(kh01, smb + K_OFF(buf, 0, kc) + sw_off(bRow0 + kb));
            ldsm4(kh23, smb + K_OFF(buf, 0, kc) + sw_off(bRow1 + kb));
            ldsm4(kl01, smb + K_OFF(buf, 1, kc) + sw_off(bRow0 + kb));
            ldsm4(kl23, smb + K_OFF(buf, 1, kc) + sw_off(bRow1 + kb));
#pragma unroll
            for (int nt = 0; nt < 4; nt++) {
                const uint32_t* bh_ = (nt < 2) ? &kh01[(nt & 1) * 2] : &kh23[(nt & 1) * 2];
                const uint32_t* bl_ = (nt < 2) ? &kl01[(nt & 1) * 2] : &kl23[(nt & 1) * 2];
                mma16816(sc[nt], aH, bh_);
                mma16816(sc[nt], aH, bl_);
                mma16816(sc[nt], aL, bh_);
            }
        }

        // ---- dots = pm * pv * scale + gl; row max ----
        float dv[4][4];
        float mx0 = -1e30f, mx1 = -1e30f;
#pragma unroll
        for (int nt = 0; nt < 4; nt++) {
            float pm0 = __expf(smv[nt][0].x - mi0) * il0;
            float pm1 = __expf(smv[nt][0].y - mi0) * il0;
            float pm2 = __expf(smv[nt][1].x - mi1) * il1;
            float pm3 = __expf(smv[nt][1].y - mi1) * il1;
            dv[nt][0] = fmaf(pm0 * sc[nt][0], SCALE_F, glv[nt][0].x);
            dv[nt][1] = fmaf(pm1 * sc[nt][1], SCALE_F, glv[nt][0].y);
            dv[nt][2] = fmaf(pm2 * sc[nt][2], SCALE_F, glv[nt][1].x);
            dv[nt][3] = fmaf(pm3 * sc[nt][3], SCALE_F, glv[nt][1].y);
            mx0 = fmaxf(mx0, fmaxf(dv[nt][0], dv[nt][1]));
            mx1 = fmaxf(mx1, fmaxf(dv[nt][2], dv[nt][3]));
        }
        mx0 = fmaxf(mx0, __shfl_xor_sync(~0u, mx0, 1));
        mx0 = fmaxf(mx0, __shfl_xor_sync(~0u, mx0, 2));
        mx1 = fmaxf(mx1, __shfl_xor_sync(~0u, mx1, 1));
        mx1 = fmaxf(mx1, __shfl_xor_sync(~0u, mx1, 2));
        if ((lane & 3) == 0) {
            redm[par * 128 + r0 * 2 + wn] = mx0;
            redm[par * 128 + (r0 + 8) * 2 + wn] = mx1;
        }
        __syncthreads();
        float mn0 = fmaxf(m_run0, fmaxf(redm[par * 128 + r0 * 2], redm[par * 128 + r0 * 2 + 1]));
        float mn1 = fmaxf(m_run1, fmaxf(redm[par * 128 + (r0 + 8) * 2],
                                        redm[par * 128 + (r0 + 8) * 2 + 1]));
        al0 = __expf(m_run0 - mn0); m_run0 = mn0;
        al1 = __expf(m_run1 - mn1); m_run1 = mn1;

        // ---- P = exp(dots - m_new); partial sums; pack A fragments ----
        float p[4][4];
        float su0 = 0.f, su1 = 0.f;
#pragma unroll
        for (int nt = 0; nt < 4; nt++) {
            p[nt][0] = __expf(dv[nt][0] - mn0);
            p[nt][1] = __expf(dv[nt][1] - mn0);
            p[nt][2] = __expf(dv[nt][2] - mn1);
            p[nt][3] = __expf(dv[nt][3] - mn1);
            su0 += p[nt][0] + p[nt][1];
            su1 += p[nt][2] + p[nt][3];
        }
        su0 += __shfl_xor_sync(~0u, su0, 1); su0 += __shfl_xor_sync(~0u, su0, 2);
        su1 += __shfl_xor_sync(~0u, su1, 1); su1 += __shfl_xor_sync(~0u, su1, 2);
        if ((lane & 3) == 0) {
            reds[par * 128 + r0 * 2 + wn] = su0;
            reds[par * 128 + (r0 + 8) * 2 + wn] = su1;
        }

        uint32_t aPh[2][4], aPl[2][4];
#pragma unroll
        for (int s = 0; s < 2; s++) {
            packPair(p[2 * s][0],     p[2 * s][1],     aPh[s][0], aPl[s][0]);
            packPair(p[2 * s][2],     p[2 * s][3],     aPh[s][1], aPl[s][1]);
            packPair(p[2 * s + 1][0], p[2 * s + 1][1], aPh[s][2], aPl[s][2]);
            packPair(p[2 * s + 1][2], p[2 * s + 1][3], aPh[s][3], aPl[s][3]);
        }

        // ---- rescale O ----
#pragma unroll
        for (int g = 0; g < 16; g++) {
            O[g][0] *= al0; O[g][1] *= al0;
            O[g][2] *= al1; O[g][3] *= al1;
        }

        // ---- O += P @ V (split both) ----
#pragma unroll
        for (int s = 0; s < 2; s++) {
            const uint32_t vkb = (uint32_t)(wn * 64 + s * 32 + (bg & 1) * 16);
#pragma unroll
            for (int g = 0; g < 8; g++) {
                const uint32_t vro = (uint32_t)(g * 16 + (bg >> 1) * 8 + br) * 128 + vkb;
                uint32_t vH[4], vL[4];
                ldsm4(vH, smb + V_OFF(buf, 0) + sw_off(vro));
                ldsm4(vL, smb + V_OFF(buf, 1) + sw_off(vro));
                mma16816(O[2 * g],     aPh[s], &vH[0]);
                mma16816(O[2 * g],     aPh[s], &vL[0]);
                mma16816(O[2 * g],     aPl[s], &vH[0]);
                mma16816(O[2 * g + 1], aPh[s], &vH[2]);
                mma16816(O[2 * g + 1], aPh[s], &vL[2]);
                mma16816(O[2 * g + 1], aPl[s], &vH[2]);
            }
        }
    }
#undef ISSUE_KV

    __syncthreads();
    // final deferred l update (jt=15 wrote parity 1)
    l_run0 = l_run0 * al0 + reds[128 + r0 * 2] + reds[128 + r0 * 2 + 1];
    l_run1 = l_run1 * al1 + reds[128 + (r0 + 8) * 2] + reds[128 + (r0 + 8) * 2 + 1];

    // cross-warp (wn) O reduction via smem, then normalize + split-bf16 store
    float* ored = (float*)(sm + 32768);   // [64][132], aliases K buffers (dead)
    if (wn == 1) {
#pragma unroll
        for (int g = 0; g < 16; g++) {
            *(float2*)&ored[r0 * 132 + g * 8 + (lane & 3) * 2] =
                make_float2(O[g][0], O[g][1]);
            *(float2*)&ored[(r0 + 8) * 132 + g * 8 + (lane & 3) * 2] =
                make_float2(O[g][2], O[g][3]);
        }
    }
    __syncthreads();
    if (wn == 0) {
        const float inv0 = 1.f / l_run0, inv1 = 1.f / l_run1;
#pragma unroll
        for (int g = 0; g < 16; g++) {
            float2 a0 = *(float2*)&ored[r0 * 132 + g * 8 + (lane & 3) * 2];
            float2 a1 = *(float2*)&ored[(r0 + 8) * 132 + g * 8 + (lane & 3) * 2];
            float x0 = (O[g][0] + a0.x) * inv0;
            float x1 = (O[g][1] + a0.y) * inv0;
            float x2 = (O[g][2] + a1.x) * inv1;
            float x3 = (O[g][3] + a1.y) * inv1;
            uint32_t hh, ll;
            size_t off = (size_t)(b * 1024 + i0 + r0) * 1024 + h * 128 + g * 8 + (lane & 3) * 2;
            packPair(x0, x1, hh, ll);
            *(uint32_t*)(g_aoh + off) = hh; *(uint32_t*)(g_aol + off) = ll;
            packPair(x2, x3, hh, ll);
            *(uint32_t*)(g_aoh + off + 8 * 1024) = hh;
            *(uint32_t*)(g_aol + off + 8 * 1024) = ll;
        }
    }
}

// ---------------- launch ----------------------------------------------------
extern "C" void kernel_launch(void* const* d_in, const int* in_sizes, int n_in,
                              void* d_out, int out_size)
{
    const float* s_v   = (const float*)d_in[0];
    const float* s_m   = (const float*)d_in[1];
    const float* g_l   = (const float*)d_in[2];
    const float* W_qkv = (const float*)d_in[3];
    const float* W_qk  = (const float*)d_in[4];
    const float* W_out = (const float*)d_in[5];
    const float* b_out = (const float*)d_in[6];
    float* out = (float*)d_out;

    float* p_sm;
    __nv_bfloat16 *p_svh, *p_svl, *p_smh, *p_sml;
    __nv_bfloat16 *p_wqkvh, *p_wqkvl, *p_wqkh, *p_wqkl, *p_wouth, *p_woutl;
    __nv_bfloat16 *p_qkh, *p_qkl, *p_aoh, *p_aol;
    cudaGetSymbolAddress((void**)&p_sm,  g_sm);
    cudaGetSymbolAddress((void**)&p_svh, g_svh);
    cudaGetSymbolAddress((void**)&p_svl, g_svl);
    cudaGetSymbolAddress((void**)&p_smh, g_smh_in);
    cudaGetSymbolAddress((void**)&p_sml, g_sml_in);
    cudaGetSymbolAddress((void**)&p_wqkvh, g_wqkvh);
    cudaGetSymbolAddress((void**)&p_wqkvl, g_wqkvl);
    cudaGetSymbolAddress((void**)&p_wqkh, g_wqkh);
    cudaGetSymbolAddress((void**)&p_wqkl, g_wqkl);
    cudaGetSymbolAddress((void**)&p_wouth, g_wouth);
    cudaGetSymbolAddress((void**)&p_woutl, g_woutl);
    cudaGetSymbolAddress((void**)&p_qkh, g_qkh);
    cudaGetSymbolAddress((void**)&p_qkl, g_qkl);
    cudaGetSymbolAddress((void**)&p_aoh, g_aoh);
    cudaGetSymbolAddress((void**)&p_aol, g_aol);

    cudaFuncSetAttribute(gemm_bf16<0>, cudaFuncAttributeMaxDynamicSharedMemorySize, GEMM_SMEM);
    cudaFuncSetAttribute(gemm_bf16<1>, cudaFuncAttributeMaxDynamicSharedMemorySize, GEMM_SMEM);
    cudaFuncSetAttribute(gemm_bf16<2>, cudaFuncAttributeMaxDynamicSharedMemorySize, GEMM_SMEM);
    cudaFuncSetAttribute(gemm_bf16<3>, cudaFuncAttributeMaxDynamicSharedMemorySize, GEMM_SMEM);
    cudaFuncSetAttribute(attn_mma, cudaFuncAttributeMaxDynamicSharedMemorySize, ATTN_SMEM);

    // 0. conversions
    asplit<<<2048, 512>>>((const float4*)s_v, (uint2*)p_svh, (uint2*)p_svl, 8 * 1024 * 1024 / 4);
    asplit<<<2048, 512>>>((const float4*)s_m, (uint2*)p_smh, (uint2*)p_sml, 8 * 1024 * 1024 / 4);
    wsplit_t<<<dim3(96, 32), 256>>>(W_qkv, 1024, 3072, p_wqkvh, p_wqkvl);
    wsplit_t<<<dim3(64, 32), 256>>>(W_qk, 1024, 2048, p_wqkh, p_wqkl);
    wsplit_t<<<dim3(32, 32), 256>>>(W_out, 1024, 1024, p_wouth, p_woutl);

    // 1. QKV projection -> split bf16 q_v|k_v + transposed v
    gemm_bf16<3><<<dim3(24, 64, 1), 512, GEMM_SMEM>>>(
        p_svh, p_svl, 1024, 0, 0, p_wqkvh, p_wqkvl, 1024, 0, 0,
        nullptr, nullptr, nullptr, 3072, 0, 1024, nullptr);
    // 2. QK projection -> split bf16 q_m|k_m
    gemm_bf16<2><<<dim3(16, 64, 1), 512, GEMM_SMEM>>>(
        p_smh, p_sml, 1024, 0, 0, p_wqkh, p_wqkl, 1024, 0, 0,
        nullptr, p_qkh, p_qkl, 2048, 0, 1024, nullptr);
    // 3. m-stream scores per (b,h) -> fp32 g_sm
    gemm_bf16<0><<<dim3(8, 8, 64), 512, GEMM_SMEM>>>(
        p_qkh, p_qkl, 2048, (size_t)NN * 2048, 128,
        p_qkh + 1024, p_qkl + 1024, 2048, (size_t)NN * 2048, 128,
        p_sm, nullptr, nullptr, 1024, (size_t)NN * NN, 128, nullptr);
    // 4. inner-softmax row stats
    row_stats<<<64 * 1024, 256>>>();
    // 5. tensor-core fused attention -> split bf16 g_aoh/g_aol
    attn_mma<<<dim3(16, NH, NB), 256, ATTN_SMEM>>>(g_l);
    // 6. output projection + bias -> out
    gemm_bf16<1><<<dim3(8, 64, 1), 512, GEMM_SMEM>>>(
        p_aoh, p_aol, 1024, 0, 0, p_wouth, p_woutl, 1024, 0, 0,
        out, nullptr, nullptr, 1024, 0, 1024, b_out);
}

// round 7
// speedup vs baseline: 3.0649x; 1.0286x over previous
#include <cuda_runtime.h>
#include <cuda_bf16.h>
#include <cstdint>
#include <math.h>

#define NB 8
#define NN 1024
#define NH 8
#define SCALE_F 0.08838834764831845f  // 128^-0.5

// ---------------- scratch (device globals; no cudaMalloc allowed) ----------
__device__ float g_sm [64ull * 1024 * 1024];  // fp32 [b*h][i][j] raw m-scores
__device__ float g_mrow[64 * 1024];
__device__ float g_invl[64 * 1024];
__device__ float g_pmax[64ull * 1024 * 8];    // per-row per-nchunk partial max
__device__ float g_psum[64ull * 1024 * 8];    // partial sumexp (vs local max)

// bf16 split planes (hi / lo)
__device__ __nv_bfloat16 g_svh[8ull * 1024 * 1024];     // s_v split
__device__ __nv_bfloat16 g_svl[8ull * 1024 * 1024];
__device__ __nv_bfloat16 g_smh_in[8ull * 1024 * 1024];  // s_m split
__device__ __nv_bfloat16 g_sml_in[8ull * 1024 * 1024];
__device__ __nv_bfloat16 g_wqkvh[3072ull * 1024];       // W_qkv^T
__device__ __nv_bfloat16 g_wqkvl[3072ull * 1024];
__device__ __nv_bfloat16 g_wqkh[2048ull * 1024];        // W_qk^T
__device__ __nv_bfloat16 g_wqkl[2048ull * 1024];
__device__ __nv_bfloat16 g_wouth[1024ull * 1024];       // W_out^T
__device__ __nv_bfloat16 g_woutl[1024ull * 1024];
__device__ __nv_bfloat16 g_qkh[8ull * 1024 * 2048];     // q_m|k_m split
__device__ __nv_bfloat16 g_qkl[8ull * 1024 * 2048];
__device__ __nv_bfloat16 g_qvh[8ull * 1024 * 3072];     // q_v|k_v|v split
__device__ __nv_bfloat16 g_qvl[8ull * 1024 * 3072];
__device__ __nv_bfloat16 g_aoh[8ull * 1024 * 1024];     // attn out split
__device__ __nv_bfloat16 g_aol[8ull * 1024 * 1024];

// ======================= helpers ===========================================
__device__ __forceinline__ uint32_t smem_u32(const void* p) {
    uint32_t a;
    asm("{ .reg .u64 t; cvta.to.shared.u64 t, %1; cvt.u32.u64 %0, t; }"
        : "=r"(a) : "l"(p));
    return a;
}
__device__ __forceinline__ void ldsm4(uint32_t* r, uint32_t addr) {
    asm volatile("ldmatrix.sync.aligned.m8n8.x4.shared.b16 {%0,%1,%2,%3}, [%4];"
                 : "=r"(r[0]), "=r"(r[1]), "=r"(r[2]), "=r"(r[3]) : "r"(addr));
}
__device__ __forceinline__ void ldsm4t(uint32_t* r, uint32_t addr) {
    asm volatile("ldmatrix.sync.aligned.m8n8.x4.trans.shared.b16 {%0,%1,%2,%3}, [%4];"
                 : "=r"(r[0]), "=r"(r[1]), "=r"(r[2]), "=r"(r[3]) : "r"(addr));
}
__device__ __forceinline__ void mma16816(float* d, const uint32_t* a, const uint32_t* b) {
    asm volatile(
        "mma.sync.aligned.m16n8k16.row.col.f32.bf16.bf16.f32 "
        "{%0,%1,%2,%3}, {%4,%5,%6,%7}, {%8,%9}, {%0,%1,%2,%3};"
        : "+f"(d[0]), "+f"(d[1]), "+f"(d[2]), "+f"(d[3])
        : "r"(a[0]), "r"(a[1]), "r"(a[2]), "r"(a[3]), "r"(b[0]), "r"(b[1]));
}
__device__ __forceinline__ uint32_t sw_off(uint32_t off) {
    return off ^ ((off >> 3) & 0x70);
}
__device__ __forceinline__ uint32_t pack2(float a, float b) {
    __nv_bfloat162 t;
    t.x = __float2bfloat16(a);
    t.y = __float2bfloat16(b);
    return *(uint32_t*)&t;
}
__device__ __forceinline__ void packPair(float a, float b, uint32_t& hi, uint32_t& lo) {
    __nv_bfloat16 h0 = __float2bfloat16(a), h1 = __float2bfloat16(b);
    __nv_bfloat162 t; t.x = h0; t.y = h1;
    hi = *(uint32_t*)&t;
    lo = pack2(a - __bfloat162float(h0), b - __bfloat162float(h1));
}
__device__ __forceinline__ void split4(const float4& v, uint32_t& h01, uint32_t& h23,
                                       uint32_t& l01, uint32_t& l23) {
    packPair(v.x, v.y, h01, l01);
    packPair(v.z, v.w, h23, l23);
}

#define CP16(dst, src) \
    asm volatile("cp.async.cg.shared.global [%0], [%1], 16;" \
                 :: "r"(dst), "l"(__cvta_generic_to_global(src)))
#define CP_COMMIT() asm volatile("cp.async.commit_group;" ::: "memory")
#define CP_WAIT1()  asm volatile("cp.async.wait_group 1;" ::: "memory")
#define CP_WAIT0()  asm volatile("cp.async.wait_group 0;" ::: "memory")

// ======================= conversion kernels ================================
__global__ __launch_bounds__(512) void asplit(const float4* __restrict__ in,
                                              uint2* __restrict__ oh,
                                              uint2* __restrict__ ol, int n4)
{
    for (int i = blockIdx.x * 512 + threadIdx.x; i < n4; i += gridDim.x * 512) {
        float4 v = in[i];
        uint32_t h01, h23, l01, l23;
        split4(v, h01, h23, l01, l23);
        oh[i] = make_uint2(h01, h23);
        ol[i] = make_uint2(l01, l23);
    }
}

__global__ __launch_bounds__(256) void wsplit_t(const float* __restrict__ W,
                                                int Kd, int Nd,
                                                __nv_bfloat16* __restrict__ Th,
                                                __nv_bfloat16* __restrict__ Tl)
{
    __shared__ float t[32][33];
    const int n0 = blockIdx.x * 32, k0 = blockIdx.y * 32;
    const int tx = threadIdx.x & 31, ty = threadIdx.x >> 5;
#pragma unroll
    for (int i = 0; i < 32; i += 8)
        t[ty + i][tx] = W[(size_t)(k0 + ty + i) * Nd + n0 + tx];
    __syncthreads();
#pragma unroll
    for (int i = 0; i < 32; i += 8) {
        float v = t[tx][ty + i];
        __nv_bfloat16 h = __float2bfloat16(v);
        __nv_bfloat16 l = __float2bfloat16(v - __bfloat162float(h));
        size_t o = (size_t)(n0 + ty + i) * Kd + k0 + tx;
        Th[o] = h;
        Tl[o] = l;
    }
}

// ======================= pipelined bf16 mma.sync GEMM ======================
// EPI: 0 fp32 C; 1 fp32 C + bias; 2 split bf16 Ch/Cl; 4 fp32 C + rowstat partials
#define ST_BYTES  65536
#define NSTAGE    3
#define GEMM_SMEM (1024 + NSTAGE * ST_BYTES)

template<int EPI>
__global__ __launch_bounds__(512, 1) void gemm_bf16(
    const __nv_bfloat16* __restrict__ Ah, const __nv_bfloat16* __restrict__ Al,
    int lda, size_t Azb, size_t Azh,
    const __nv_bfloat16* __restrict__ Bh, const __nv_bfloat16* __restrict__ Bl,
    int ldb, size_t Bzb, size_t Bzh,
    float* __restrict__ C, __nv_bfloat16* __restrict__ Ch,
    __nv_bfloat16* __restrict__ Cl,
    int ldc, size_t Cz, int K, const float* __restrict__ bias)
{
    extern __shared__ char smraw[];
    uint32_t raw = smem_u32(smraw);
    char* sm = smraw + ((1024u - (raw & 1023u)) & 1023u);
    const uint32_t smb = smem_u32(sm);

    const int tid = threadIdx.x;
    const int wid = tid >> 5, lane = tid & 31;
    const int wm = wid & 3, wn = wid >> 2;
    const int bn = blockIdx.x * 128, bm = blockIdx.y * 128;
    const int z = blockIdx.z;

    const size_t zao = (size_t)(z >> 3) * Azb + (size_t)(z & 7) * Azh;
    const size_t zbo = (size_t)(z >> 3) * Bzb + (size_t)(z & 7) * Bzh;

    const __nv_bfloat16* pls[4] = {
        Ah + zao + (size_t)bm * lda, Al + zao + (size_t)bm * lda,
        Bh + zbo + (size_t)bn * ldb, Bl + zbo + (size_t)bn * ldb };

    const int nchunks = K >> 6;

#define ISSUE_STAGE(cc_) do {                                                  \
        int _c = (cc_);                                                        \
        if (_c < nchunks) {                                                    \
            uint32_t sb = smb + (uint32_t)(_c % NSTAGE) * ST_BYTES;            \
            int _k0 = _c << 6;                                                 \
            _Pragma("unroll")                                                  \
            for (int it = 0; it < 8; ++it) {                                   \
                int pl = it >> 1;                                              \
                int cidx = tid + (it & 1) * 512;                               \
                int row = cidx >> 3, c16 = cidx & 7;                           \
                int ld = (pl < 2) ? lda : ldb;                                 \
                const __nv_bfloat16* g = pls[pl] + (size_t)row * ld + _k0 + c16 * 8; \
                uint32_t d = sb + pl * 16384 + sw_off(row * 128 + c16 * 16);   \
                CP16(d, g);                                                    \
            }                                                                  \
        }                                                                      \
        CP_COMMIT();                                                           \
    } while (0)

    float acc[2][4][4];
#pragma unroll
    for (int mt = 0; mt < 2; mt++)
#pragma unroll
        for (int nt = 0; nt < 4; nt++)
#pragma unroll
            for (int i = 0; i < 4; i++) acc[mt][nt][i] = 0.f;

    ISSUE_STAGE(0);
    ISSUE_STAGE(1);

    const uint32_t arow0 = wm * 32 + (lane & 15);
    const uint32_t akhalf = (lane >> 4) * 16;
    const uint32_t bg = lane >> 3, br = lane & 7;
    const uint32_t brow0 = wn * 32 + (bg >> 1) * 8 + br;
    const uint32_t bkhalf = (bg & 1) * 16;

    for (int c = 0; c < nchunks; ++c) {
        CP_WAIT1();
        __syncthreads();
        ISSUE_STAGE(c + 2);

        const uint32_t so = smb + (uint32_t)(c % NSTAGE) * ST_BYTES;
        const uint32_t aHb = so, aLb = so + 16384;
        const uint32_t bHb = so + 32768, bLb = so + 49152;

#pragma unroll
        for (int k16 = 0; k16 < 4; ++k16) {
            const uint32_t kb = k16 * 32;
            uint32_t offA0 = sw_off(arow0 * 128 + kb + akhalf);
            uint32_t offA1 = sw_off((arow0 + 16) * 128 + kb + akhalf);
            uint32_t offB0 = sw_off(brow0 * 128 + kb + bkhalf);
            uint32_t offB1 = sw_off((brow0 + 16) * 128 + kb + bkhalf);

            uint32_t aH[2][4], aL[2][4];
            ldsm4(aH[0], aHb + offA0); ldsm4(aH[1], aHb + offA1);
            ldsm4(aL[0], aLb + offA0); ldsm4(aL[1], aLb + offA1);

            uint32_t bH01[4], bH23[4], bL01[4], bL23[4];
            ldsm4(bH01, bHb + offB0); ldsm4(bH23, bHb + offB1);
            ldsm4(bL01, bLb + offB0); ldsm4(bL23, bLb + offB1);

#pragma unroll
            for (int mt = 0; mt < 2; mt++) {
#pragma unroll
                for (int nt = 0; nt < 4; nt++) {
                    const uint32_t* bhp = (nt < 2) ? &bH01[(nt & 1) * 2] : &bH23[(nt & 1) * 2];
                    const uint32_t* blp = (nt < 2) ? &bL01[(nt & 1) * 2] : &bL23[(nt & 1) * 2];
                    mma16816(acc[mt][nt], aH[mt], bhp);
                    mma16816(acc[mt][nt], aH[mt], blp);
                    mma16816(acc[mt][nt], aL[mt], bhp);
                }
            }
        }
        __syncthreads();
    }
#undef ISSUE_STAGE

    const int rgrp = lane >> 2, cpair = (lane & 3) * 2;
#pragma unroll
    for (int mt = 0; mt < 2; mt++) {
#pragma unroll
        for (int nt = 0; nt < 4; nt++) {
            int row0 = bm + wm * 32 + mt * 16 + rgrp;
            int col = bn + wn * 32 + nt * 8 + cpair;
            float x0 = acc[mt][nt][0], x1 = acc[mt][nt][1];
            float x2 = acc[mt][nt][2], x3 = acc[mt][nt][3];
            if (EPI == 2) {
                size_t o0 = (size_t)z * Cz + (size_t)row0 * ldc + col;
                size_t o1 = o0 + 8ull * ldc;
                uint32_t hh, ll;
                packPair(x0, x1, hh, ll);
                *(uint32_t*)(Ch + o0) = hh; *(uint32_t*)(Cl + o0) = ll;
                packPair(x2, x3, hh, ll);
                *(uint32_t*)(Ch + o1) = hh; *(uint32_t*)(Cl + o1) = ll;
            } else {
                float b0 = 0.f, b1 = 0.f;
                if (EPI == 1) { b0 = bias[col]; b1 = bias[col + 1]; }
                float2 v0, v1;
                v0.x = x0 + b0; v0.y = x1 + b1;
                v1.x = x2 + b0; v1.y = x3 + b1;
                float* Cb = C + (size_t)z * Cz;
                *(float2*)(Cb + (size_t)row0 * ldc + col) = v0;
                *(float2*)(Cb + (size_t)(row0 + 8) * ldc + col) = v1;
            }
        }
    }

    if (EPI == 4) {
        // per-CTA row-stat partials: max & sumexp over this 128-col tile
        float* redm_ = (float*)sm;              // [128][4]
        float* redsu = (float*)(sm + 2048);     // [128][4]
#pragma unroll
        for (int mt = 0; mt < 2; mt++)
#pragma unroll
            for (int hf = 0; hf < 2; hf++) {
                int lrow = wm * 32 + mt * 16 + hf * 8 + rgrp;
                float mx = -1e30f;
#pragma unroll
                for (int nt = 0; nt < 4; nt++)
                    mx = fmaxf(mx, fmaxf(acc[mt][nt][hf * 2], acc[mt][nt][hf * 2 + 1]));
                mx = fmaxf(mx, __shfl_xor_sync(~0u, mx, 1));
                mx = fmaxf(mx, __shfl_xor_sync(~0u, mx, 2));
                if ((lane & 3) == 0) redm_[lrow * 4 + wn] = mx;
            }
        __syncthreads();
#pragma unroll
        for (int mt = 0; mt < 2; mt++)
#pragma unroll
            for (int hf = 0; hf < 2; hf++) {
                int lrow = wm * 32 + mt * 16 + hf * 8 + rgrp;
                float rm = fmaxf(fmaxf(redm_[lrow * 4], redm_[lrow * 4 + 1]),
                                 fmaxf(redm_[lrow * 4 + 2], redm_[lrow * 4 + 3]));
                float su = 0.f;
#pragma unroll
                for (int nt = 0; nt < 4; nt++)
                    su += __expf(acc[mt][nt][hf * 2] - rm) +
                          __expf(acc[mt][nt][hf * 2 + 1] - rm);
                su += __shfl_xor_sync(~0u, su, 1);
                su += __shfl_xor_sync(~0u, su, 2);
                if ((lane & 3) == 0) redsu[lrow * 4 + wn] = su;
            }
        __syncthreads();
        if (tid < 128) {
            float m4 = fmaxf(fmaxf(redm_[tid * 4], redm_[tid * 4 + 1]),
                             fmaxf(redm_[tid * 4 + 2], redm_[tid * 4 + 3]));
            float s4 = redsu[tid * 4] + redsu[tid * 4 + 1] +
                       redsu[tid * 4 + 2] + redsu[tid * 4 + 3];
            size_t o = ((size_t)z * 1024 + bm + tid) * 8 + blockIdx.x;
            g_pmax[o] = m4;
            g_psum[o] = s4;
        }
    }
}

// ---------------- combine row-stat partials --------------------------------
__global__ __launch_bounds__(256) void row_combine()
{
    const int row = blockIdx.x * 256 + threadIdx.x;   // 0..65535
    const float* pm = g_pmax + (size_t)row * 8;
    const float* ps = g_psum + (size_t)row * 8;
    float m = pm[0];
#pragma unroll
    for (int j = 1; j < 8; ++j) m = fmaxf(m, pm[j]);
    float l = 0.f;
#pragma unroll
    for (int j = 0; j < 8; ++j) l += ps[j] * __expf(pm[j] - m);
    g_mrow[row] = m;
    g_invl[row] = 1.f / l;
}

// ================= tensor-core fused flash attention =======================
// CTA: 64 queries x head x batch, 256 threads (8 warps: 4 along m x 2 along j)
// smem: Q planes 32KB | K 2x32KB | V 2x32KB ([j][d-half] 128B rows) | red 2KB
#define Q_OFF(hl, kc)      ((uint32_t)(((hl) * 2 + (kc)) * 8192))
#define K_OFF(buf, hl, kc) ((uint32_t)(32768 + (buf) * 32768 + ((hl) * 2 + (kc)) * 8192))
#define V_OFF(buf, hl)     ((uint32_t)(98304 + (buf) * 32768 + (hl) * 16384))
#define REDM_OFF 163840
#define REDS_OFF 164864
#define ATTN_SMEM (1024 + 165888)

__global__ __launch_bounds__(256, 1) void attn_mma(const float* __restrict__ gl)
{
    extern __shared__ char smraw[];
    uint32_t raw = smem_u32(smraw);
    char* sm = smraw + ((1024u - (raw & 1023u)) & 1023u);
    const uint32_t smb = smem_u32(sm);
    float* redm = (float*)(sm + REDM_OFF);
    float* reds = (float*)(sm + REDS_OFF);

    const int tid = threadIdx.x, lane = tid & 31, wid = tid >> 5;
    const int wm = wid & 3, wn = wid >> 2;
    const int bg = lane >> 3, br = lane & 7;
    const int i0 = blockIdx.x * 64, h = blockIdx.y, b = blockIdx.z;
    const int bh = b * 8 + h;

    const __nv_bfloat16* qsrc[2] = {
        g_qvh + (size_t)(b * 1024 + i0) * 3072 + h * 128,
        g_qvl + (size_t)(b * 1024 + i0) * 3072 + h * 128 };
    const __nv_bfloat16* ksrc[2] = {
        g_qvh + (size_t)(b * 1024) * 3072 + 1024 + h * 128,
        g_qvl + (size_t)(b * 1024) * 3072 + 1024 + h * 128 };
    const __nv_bfloat16* vsrc[2] = {
        g_qvh + (size_t)(b * 1024) * 3072 + 2048 + h * 128,
        g_qvl + (size_t)(b * 1024) * 3072 + 2048 + h * 128 };
    const float* Sm = g_sm + ((size_t)bh << 20);
    const float* GL = gl + ((size_t)bh << 20);

#define ISSUE_KV(j0_, buf_) do {                                               \
        _Pragma("unroll")                                                      \
        for (int i = 0; i < 8; ++i) {                                          \
            int c = tid + i * 256;                                             \
            int hl = c >> 10, rem = c & 1023;                                  \
            int row = rem >> 4, seg = rem & 15;                                \
            CP16(smb + K_OFF(buf_, hl, seg >> 3) + sw_off(row * 128 + (seg & 7) * 16), \
                 ksrc[hl] + (size_t)((j0_) + row) * 3072 + seg * 8);           \
        }                                                                      \
        _Pragma("unroll")                                                      \
        for (int i = 0; i < 8; ++i) {                                          \
            int c = tid + i * 256;                                             \
            int hl = c >> 10, rem = c & 1023;                                  \
            int row = rem >> 4, seg = rem & 15;                                \
            CP16(smb + V_OFF(buf_, hl) + (seg >> 3) * 8192 + sw_off(row * 128 + (seg & 7) * 16), \
                 vsrc[hl] + (size_t)((j0_) + row) * 3072 + seg * 8);           \
        }                                                                      \
    } while (0)

    // Q load + KV tile 0
#pragma unroll
    for (int i = 0; i < 8; ++i) {
        int c = tid + i * 256;
        int hl = c >> 10, rem = c & 1023;
        int row = rem >> 4, seg = rem & 15;
        CP16(smb + Q_OFF(hl, seg >> 3) + sw_off(row * 128 + (seg & 7) * 16),
             qsrc[hl] + (size_t)row * 3072 + seg * 8);
    }
    ISSUE_KV(0, 0);
    CP_COMMIT();

    const int r0 = wm * 16 + (lane >> 2);
    const float mi0 = g_mrow[bh * 1024 + i0 + r0];
    const float mi1 = g_mrow[bh * 1024 + i0 + r0 + 8];
    const float il0 = g_invl[bh * 1024 + i0 + r0];
    const float il1 = g_invl[bh * 1024 + i0 + r0 + 8];

    float O[16][4];
#pragma unroll
    for (int g = 0; g < 16; g++)
#pragma unroll
        for (int i = 0; i < 4; i++) O[g][i] = 0.f;
    float m_run0 = -1e30f, m_run1 = -1e30f, l_run0 = 0.f, l_run1 = 0.f;
    float al0 = 0.f, al1 = 0.f;

    const uint32_t aRow = (uint32_t)(wm * 16 + (lane & 15)) * 128 + (lane >> 4) * 16;
    const uint32_t bRow0 = (uint32_t)(wn * 32 + (bg >> 1) * 8 + br) * 128 + (bg & 1) * 16;
    const uint32_t bRow1 = bRow0 + 16 * 128;
    // trans-ldsm address for V: rows j, 16B chunk pairs along d
    const uint32_t vRowBase = (uint32_t)(lane & 15) * 128 + (lane >> 4) * 16;

    for (int jt = 0; jt < 16; ++jt) {
        const int j0 = jt * 64, buf = jt & 1, par = jt & 1;
        CP_WAIT0();
        __syncthreads();
        if (jt < 15) { ISSUE_KV(j0 + 64, buf ^ 1); CP_COMMIT(); }

        if (jt > 0) {
            int pp = par ^ 1;
            l_run0 = l_run0 * al0 + reds[pp * 128 + r0 * 2] + reds[pp * 128 + r0 * 2 + 1];
            l_run1 = l_run1 * al1 + reds[pp * 128 + (r0 + 8) * 2] + reds[pp * 128 + (r0 + 8) * 2 + 1];
        }

        const int colb = j0 + wn * 32 + (lane & 3) * 2;
        float2 smv[4][2], glv[4][2];
#pragma unroll
        for (int nt = 0; nt < 4; nt++) {
            smv[nt][0] = *(const float2*)(Sm + (size_t)(i0 + r0) * 1024 + colb + nt * 8);
            smv[nt][1] = *(const float2*)(Sm + (size_t)(i0 + r0 + 8) * 1024 + colb + nt * 8);
            glv[nt][0] = *(const float2*)(GL + (size_t)(i0 + r0) * 1024 + colb + nt * 8);
            glv[nt][1] = *(const float2*)(GL + (size_t)(i0 + r0 + 8) * 1024 + colb + nt * 8);
        }

        float sc[4][4];
#pragma unroll
        for (int nt = 0; nt < 4; nt++)
#pragma unroll
            for (int i = 0; i < 4; i++) sc[nt][i] = 0.f;

#pragma unroll
        for (int s = 0; s < 8; ++s) {
            const int kc = s >> 2;
            const uint32_t kb = (uint32_t)(s & 3) * 32;
            uint32_t aH[4], aL[4];
            ldsm4(aH, smb + Q_OFF(0, kc) + sw_off(aRow + kb));
            ldsm4(aL, smb + Q_OFF(1, kc) + sw_off(aRow + kb));
            uint32_t kh01[4], kh23[4], kl01[4], kl23[4];
            ldsm4(kh01, smb + K_OFF(buf, 0, kc) + sw_off(bRow0 + kb));
            ldsm4(kh23, smb + K_OFF(buf, 0, kc) + sw_off(bRow1 + kb));
            ldsm4(kl01, smb + K_OFF(buf, 1, kc) + sw_off(bRow0 + kb));
            ldsm4(kl23, smb + K_OFF(buf, 1, kc) + sw_off(bRow1 + kb));
#pragma unroll
            for (int nt = 0; nt < 4; nt++) {
                const uint32_t* bhp = (nt < 2) ? &kh01[(nt & 1) * 2] : &kh23[(nt & 1) * 2];
                const uint32_t* blp = (nt < 2) ? &kl01[(nt & 1) * 2] : &kl23[(nt & 1) * 2];
                mma16816(sc[nt], aH, bhp);
                mma16816(sc[nt], aH, blp);
                mma16816(sc[nt], aL, bhp);
            }
        }

        float dv[4][4];
        float mx0 = -1e30f, mx1 = -1e30f;
#pragma unroll
        for (int nt = 0; nt < 4; nt++) {
            float pm0 = __expf(smv[nt][0].x - mi0) * il0;
            float pm1 = __expf(smv[nt][0].y - mi0) * il0;
            float pm2 = __expf(smv[nt][1].x - mi1) * il1;
            float pm3 = __expf(smv[nt][1].y - mi1) * il1;
            dv[nt][0] = fmaf(pm0 * sc[nt][0], SCALE_F, glv[nt][0].x);
            dv[nt][1] = fmaf(pm1 * sc[nt][1], SCALE_F, glv[nt][0].y);
            dv[nt][2] = fmaf(pm2 * sc[nt][2], SCALE_F, glv[nt][1].x);
            dv[nt][3] = fmaf(pm3 * sc[nt][3], SCALE_F, glv[nt][1].y);
            mx0 = fmaxf(mx0, fmaxf(dv[nt][0], dv[nt][1]));
            mx1 = fmaxf(mx1, fmaxf(dv[nt][2], dv[nt][3]));
        }
        mx0 = fmaxf(mx0, __shfl_xor_sync(~0u, mx0, 1));
        mx0 = fmaxf(mx0, __shfl_xor_sync(~0u, mx0, 2));
        mx1 = fmaxf(mx1, __shfl_xor_sync(~0u, mx1, 1));
        mx1 = fmaxf(mx1, __shfl_xor_sync(~0u, mx1, 2));
        if ((lane & 3) == 0) {
            redm[par * 128 + r0 * 2 + wn] = mx0;
            redm[par * 128 + (r0 + 8) * 2 + wn] = mx1;
        }
        __syncthreads();
        float mn0 = fmaxf(m_run0, fmaxf(redm[par * 128 + r0 * 2], redm[par * 128 + r0 * 2 + 1]));
        float mn1 = fmaxf(m_run1, fmaxf(redm[par * 128 + (r0 + 8) * 2],
                                        redm[par * 128 + (r0 + 8) * 2 + 1]));
        al0 = __expf(m_run0 - mn0); m_run0 = mn0;
        al1 = __expf(m_run1 - mn1); m_run1 = mn1;

        float p[4][4];
        float su0 = 0.f, su1 = 0.f;
#pragma unroll
        for (int nt = 0; nt < 4; nt++) {
            p[nt][0] = __expf(dv[nt][0] - mn0);
            p[nt][1] = __expf(dv[nt][1] - mn0);
            p[nt][2] = __expf(dv[nt][2] - mn1);
            p[nt][3] = __expf(dv[nt][3] - mn1);
            su0 += p[nt][0] + p[nt][1];
            su1 += p[nt][2] + p[nt][3];
        }
        su0 += __shfl_xor_sync(~0u, su0, 1); su0 += __shfl_xor_sync(~0u, su0, 2);
        su1 += __shfl_xor_sync(~0u, su1, 1); su1 += __shfl_xor_sync(~0u, su1, 2);
        if ((lane & 3) == 0) {
            reds[par * 128 + r0 * 2 + wn] = su0;
            reds[par * 128 + (r0 + 8) * 2 + wn] = su1;
        }

        uint32_t aPh[2][4], aPl[2][4];
#pragma unroll
        for (int s = 0; s < 2; s++) {
            packPair(p[2 * s][0],     p[2 * s][1],     aPh[s][0], aPl[s][0]);
            packPair(p[2 * s][2],     p[2 * s][3],     aPh[s][1], aPl[s][1]);
            packPair(p[2 * s + 1][0], p[2 * s + 1][1], aPh[s][2], aPl[s][2]);
            packPair(p[2 * s + 1][2], p[2 * s + 1][3], aPh[s][3], aPl[s][3]);
        }

#pragma unroll
        for (int g = 0; g < 16; g++) {
            O[g][0] *= al0; O[g][1] *= al0;
            O[g][2] *= al1; O[g][3] *= al1;
        }

        // ---- O += P @ V via trans-ldmatrix on [j][d] tiles ----
#pragma unroll
        for (int s = 0; s < 2; s++) {
            const uint32_t vro = (uint32_t)(wn * 32 + s * 16) * 128 + vRowBase;
#pragma unroll
            for (int dh = 0; dh < 2; dh++) {
#pragma unroll
                for (int c4 = 0; c4 < 4; c4++) {
                    uint32_t off = sw_off(vro + c4 * 32) + dh * 8192;
                    uint32_t vH[4], vL[4];
                    ldsm4t(vH, smb + V_OFF(buf, 0) + off);
                    ldsm4t(vL, smb + V_OFF(buf, 1) + off);
                    const int g = dh * 8 + c4 * 2;
                    mma16816(O[g],     aPh[s], &vH[0]);
                    mma16816(O[g],     aPh[s], &vL[0]);
                    mma16816(O[g],     aPl[s], &vH[0]);
                    mma16816(O[g + 1], aPh[s], &vH[2]);
                    mma16816(O[g + 1], aPh[s], &vL[2]);
                    mma16816(O[g + 1], aPl[s], &vH[2]);
                }
            }
        }
    }
#undef ISSUE_KV

    __syncthreads();
    l_run0 = l_run0 * al0 + reds[128 + r0 * 2] + reds[128 + r0 * 2 + 1];
    l_run1 = l_run1 * al1 + reds[128 + (r0 + 8) * 2] + reds[128 + (r0 + 8) * 2 + 1];

    float* ored = (float*)(sm + 32768);   // [64][132], aliases K buffers (dead)
    if (wn == 1) {
#pragma unroll
        for (int g = 0; g < 16; g++) {
            *(float2*)&ored[r0 * 132 + g * 8 + (lane & 3) * 2] =
                make_float2(O[g][0], O[g][1]);
            *(float2*)&ored[(r0 + 8) * 132 + g * 8 + (lane & 3) * 2] =
                make_float2(O[g][2], O[g][3]);
        }
    }
    __syncthreads();
    if (wn == 0) {
        const float inv0 = 1.f / l_run0, inv1 = 1.f / l_run1;
#pragma unroll
        for (int g = 0; g < 16; g++) {
            float2 a0 = *(float2*)&ored[r0 * 132 + g * 8 + (lane & 3) * 2];
            float2 a1 = *(float2*)&ored[(r0 + 8) * 132 + g * 8 + (lane & 3) * 2];
            float x0 = (O[g][0] + a0.x) * inv0;
            float x1 = (O[g][1] + a0.y) * inv0;
            float x2 = (O[g][2] + a1.x) * inv1;
            float x3 = (O[g][3] + a1.y) * inv1;
            uint32_t hh, ll;
            size_t off = (size_t)(b * 1024 + i0 + r0) * 1024 + h * 128 + g * 8 + (lane & 3) * 2;
            packPair(x0, x1, hh, ll);
            *(uint32_t*)(g_aoh + off) = hh; *(uint32_t*)(g_aol + off) = ll;
            packPair(x2, x3, hh, ll);
            *(uint32_t*)(g_aoh + off + 8 * 1024) = hh;
            *(uint32_t*)(g_aol + off + 8 * 1024) = ll;
        }
    }
}

// ---------------- launch ----------------------------------------------------
extern "C" void kernel_launch(void* const* d_in, const int* in_sizes, int n_in,
                              void* d_out, int out_size)
{
    const float* s_v   = (const float*)d_in[0];
    const float* s_m   = (const float*)d_in[1];
    const float* g_l   = (const float*)d_in[2];
    const float* W_qkv = (const float*)d_in[3];
    const float* W_qk  = (const float*)d_in[4];
    const float* W_out = (const float*)d_in[5];
    const float* b_out = (const float*)d_in[6];
    float* out = (float*)d_out;

    float* p_sm;
    __nv_bfloat16 *p_svh, *p_svl, *p_smh, *p_sml;
    __nv_bfloat16 *p_wqkvh, *p_wqkvl, *p_wqkh, *p_wqkl, *p_wouth, *p_woutl;
    __nv_bfloat16 *p_qkh, *p_qkl, *p_qvh, *p_qvl, *p_aoh, *p_aol;
    cudaGetSymbolAddress((void**)&p_sm,  g_sm);
    cudaGetSymbolAddress((void**)&p_svh, g_svh);
    cudaGetSymbolAddress((void**)&p_svl, g_svl);
    cudaGetSymbolAddress((void**)&p_smh, g_smh_in);
    cudaGetSymbolAddress((void**)&p_sml, g_sml_in);
    cudaGetSymbolAddress((void**)&p_wqkvh, g_wqkvh);
    cudaGetSymbolAddress((void**)&p_wqkvl, g_wqkvl);
    cudaGetSymbolAddress((void**)&p_wqkh, g_wqkh);
    cudaGetSymbolAddress((void**)&p_wqkl, g_wqkl);
    cudaGetSymbolAddress((void**)&p_wouth, g_wouth);
    cudaGetSymbolAddress((void**)&p_woutl, g_woutl);
    cudaGetSymbolAddress((void**)&p_qkh, g_qkh);
    cudaGetSymbolAddress((void**)&p_qkl, g_qkl);
    cudaGetSymbolAddress((void**)&p_qvh, g_qvh);
    cudaGetSymbolAddress((void**)&p_qvl, g_qvl);
    cudaGetSymbolAddress((void**)&p_aoh, g_aoh);
    cudaGetSymbolAddress((void**)&p_aol, g_aol);

    cudaFuncSetAttribute(gemm_bf16<1>, cudaFuncAttributeMaxDynamicSharedMemorySize, GEMM_SMEM);
    cudaFuncSetAttribute(gemm_bf16<2>, cudaFuncAttributeMaxDynamicSharedMemorySize, GEMM_SMEM);
    cudaFuncSetAttribute(gemm_bf16<4>, cudaFuncAttributeMaxDynamicSharedMemorySize, GEMM_SMEM);
    cudaFuncSetAttribute(attn_mma, cudaFuncAttributeMaxDynamicSharedMemorySize, ATTN_SMEM);

    // 0. conversions
    asplit<<<2048, 512>>>((const float4*)s_v, (uint2*)p_svh, (uint2*)p_svl, 8 * 1024 * 1024 / 4);
    asplit<<<2048, 512>>>((const float4*)s_m, (uint2*)p_smh, (uint2*)p_sml, 8 * 1024 * 1024 / 4);
    wsplit_t<<<dim3(96, 32), 256>>>(W_qkv, 1024, 3072, p_wqkvh, p_wqkvl);
    wsplit_t<<<dim3(64, 32), 256>>>(W_qk, 1024, 2048, p_wqkh, p_wqkl);
    wsplit_t<<<dim3(32, 32), 256>>>(W_out, 1024, 1024, p_wouth, p_woutl);

    // 1. QKV projection -> split bf16 [8192][3072] (q_v|k_v|v, coalesced)
    gemm_bf16<2><<<dim3(24, 64, 1), 512, GEMM_SMEM>>>(
        p_svh, p_svl, 1024, 0, 0, p_wqkvh, p_wqkvl, 1024, 0, 0,
        nullptr, p_qvh, p_qvl, 3072, 0, 1024, nullptr);
    // 2. QK projection -> split bf16 q_m|k_m
    gemm_bf16<2><<<dim3(16, 64, 1), 512, GEMM_SMEM>>>(
        p_smh, p_sml, 1024, 0, 0, p_wqkh, p_wqkl, 1024, 0, 0,
        nullptr, p_qkh, p_qkl, 2048, 0, 1024, nullptr);
    // 3. m-stream scores per (b,h) -> fp32 g_sm + fused row-stat partials
    gemm_bf16<4><<<dim3(8, 8, 64), 512, GEMM_SMEM>>>(
        p_qkh, p_qkl, 2048, (size_t)NN * 2048, 128,
        p_qkh + 1024, p_qkl + 1024, 2048, (size_t)NN * 2048, 128,
        p_sm, nullptr, nullptr, 1024, (size_t)NN * NN, 128, nullptr);
    // 4. combine partials -> g_mrow / g_invl
    row_combine<<<256, 256>>>();
    // 5. tensor-core fused attention -> split bf16 g_aoh/g_aol
    attn_mma<<<dim3(16, NH, NB), 256, ATTN_SMEM>>>(g_l);
    // 6. output projection + bias -> out
    gemm_bf16<1><<<dim3(8, 64, 1), 512, GEMM_SMEM>>>(
        p_aoh, p_aol, 1024, 0, 0, p_wouth, p_woutl, 1024, 0, 0,
        out, nullptr, nullptr, 1024, 0, 1024, b_out);
}